// round 13
// baseline (speedup 1.0000x reference)
#include <cuda_runtime.h>
#include <cuda_fp16.h>

#define N_USERS  100000
#define N_TOTAL  150000
#define DIM      64
#define BATCH    4096
#define NNZ_MAX  1400000     // 1.2M edges + up to 150k pad slots

#define SCAN_TILE 4096                                  // 1024 threads x 4 items
#define NB ((N_TOTAL + SCAN_TILE - 1) / SCAN_TILE)      // 37 blocks (all resident)

// Scaled-space embeddings X_k = d_inv ⊙ E_k, fp16, with one extra zero row
// (index N_TOTAL) used as the gather target of pad edges. All __device__
// globals are zero-initialized at module load; the sentinel rows are never
// written, so they stay zero. g_cnt and the scan flags are re-zeroed each call
// by the aux lane of k_prep_scatter (for the NEXT call).
__device__ __half g_X0[(N_TOTAL + 1) * DIM];
__device__ __half g_XA[(N_TOTAL + 1) * DIM];
__device__ __half g_XB[(N_TOTAL + 1) * DIM];
__device__ float g_dinv[N_TOTAL];        // (deg+1e-9)^-0.5
__device__ float g_dpos[N_TOTAL];        // (deg+1e-9)^+0.5  (to unscale)
__device__ int   g_cnt[N_TOTAL];         // true row degree (zeroed for next call)
__device__ int   g_rowptr[N_TOTAL + 1];  // padded exclusive scan (+ total at end)
__device__ int   g_rank[NNZ_MAX];        // intra-row rank per edge (from hist)
__device__ int   g_ecol[NNZ_MAX];        // CSR column indices; pad slots = N_TOTAL
__device__ int   g_blockAgg[64];
__device__ int   g_aggReady[64];

__device__ __forceinline__ __half2 u2h2(unsigned u) {
    __half2 h; *reinterpret_cast<unsigned*>(&h) = u; return h;
}
__device__ __forceinline__ unsigned h22u(__half2 h) {
    return *reinterpret_cast<unsigned*>(&h);
}

// ---------------------------------------------------------------------------
// histogram of row ids, capturing each edge's intra-row rank (4 edges/thread)
__global__ void k_hist(const int* __restrict__ row, int nnz) {
    int t = blockIdx.x * blockDim.x + threadIdx.x;
    int base = t * 4;
    if (base + 4 <= nnz) {
        int4 r = __ldg(reinterpret_cast<const int4*>(row + base));
        int4 k;
        k.x = atomicAdd(&g_cnt[r.x], 1);
        k.y = atomicAdd(&g_cnt[r.y], 1);
        k.z = atomicAdd(&g_cnt[r.z], 1);
        k.w = atomicAdd(&g_cnt[r.w], 1);
        *reinterpret_cast<int4*>(g_rank + base) = k;
    } else {
        for (int e = base; e < nnz; e++)
            g_rank[e] = atomicAdd(&g_cnt[__ldg(row + e)], 1);
    }
}

// single-pass exclusive scan of padded counts -> rowptr (incl. total at
// rowptr[N_TOTAL]); derives degree normalizers; writes pad-edge sentinels.
__global__ void k_scan() {
    __shared__ int warpsum[32];
    __shared__ int s_aggs[64];
    __shared__ int s_prev;
    int tid  = threadIdx.x;
    int lane = tid & 31, wid = tid >> 5;
    int base = blockIdx.x * SCAN_TILE + tid * 4;

    int cc[4], cp[4];
#pragma unroll
    for (int k = 0; k < 4; k++) {
        int idx = base + k;
        cc[k] = (idx < N_TOTAL) ? g_cnt[idx] : 0;
        cp[k] = (cc[k] + 1) & ~1;                 // padded to even
    }
    int t = cp[0] + cp[1] + cp[2] + cp[3];

    int x = t;
#pragma unroll
    for (int o = 1; o < 32; o <<= 1) {
        int y = __shfl_up_sync(0xffffffffu, x, o);
        if (lane >= o) x += y;
    }
    if (lane == 31) warpsum[wid] = x;
    __syncthreads();
    if (wid == 0) {
        int v = warpsum[lane];
#pragma unroll
        for (int o = 1; o < 32; o <<= 1) {
            int y = __shfl_up_sync(0xffffffffu, v, o);
            if (lane >= o) v += y;
        }
        warpsum[lane] = v;
    }
    __syncthreads();

    if (tid == 0) {
        g_blockAgg[blockIdx.x] = warpsum[31];
        __threadfence();
        atomicExch(&g_aggReady[blockIdx.x], 1);
    }
    if (tid < blockIdx.x) {
        while (atomicAdd(&g_aggReady[tid], 0) == 0) { }
        __threadfence();
        s_aggs[tid] = g_blockAgg[tid];
    }
    __syncthreads();
    if (tid == 0) {
        int p = 0;
        for (int j = 0; j < blockIdx.x; j++) p += s_aggs[j];
        s_prev = p;
    }
    __syncthreads();

    int woff = (wid == 0) ? 0 : warpsum[wid - 1];
    int run = s_prev + woff + (x - t);
#pragma unroll
    for (int k = 0; k < 4; k++) {
        int idx = base + k;
        if (idx < N_TOTAL) {
            g_rowptr[idx] = run;
            float degf = (float)cc[k] + 1e-9f;
            g_dinv[idx] = rsqrtf(degf);
            g_dpos[idx] = sqrtf(degf);
            if (cc[k] & 1) g_ecol[run + cc[k]] = N_TOTAL;   // pad -> zero row
            run += cp[k];
            if (idx == N_TOTAL - 1) g_rowptr[N_TOTAL] = run;  // total
        }
    }
}

// ---------------------------------------------------------------------------
// Fused scatter + prep + counter-rezero, blocks interleaved by modulo so every
// scheduling wave mixes L2-latency-bound scatter with DRAM-streaming prep.
__global__ void k_prep_scatter(const float4* __restrict__ E0,
                               const int* __restrict__ row,
                               const int* __restrict__ col,
                               int nnz, int sBlocks, int zBlocks, int pBlocks) {
    unsigned b = blockIdx.x;
    if ((b & 3u) == 0u) {
        int aux = b >> 2;
        if (aux < sBlocks) {
            // ---- scatter: 4 edges/thread, slot = rowptr[row] + rank[edge]
            int t = aux * blockDim.x + threadIdx.x;
            int base = t * 4;
            if (base + 4 <= nnz) {
                int4 r = __ldg(reinterpret_cast<const int4*>(row + base));
                int4 c = __ldg(reinterpret_cast<const int4*>(col + base));
                int4 k = *reinterpret_cast<const int4*>(g_rank + base);
                g_ecol[__ldg(g_rowptr + r.x) + k.x] = c.x;
                g_ecol[__ldg(g_rowptr + r.y) + k.y] = c.y;
                g_ecol[__ldg(g_rowptr + r.z) + k.z] = c.z;
                g_ecol[__ldg(g_rowptr + r.w) + k.w] = c.w;
            } else {
                for (int e = base; e < nnz; e++) {
                    int rr = __ldg(row + e);
                    g_ecol[__ldg(g_rowptr + rr) + g_rank[e]] = __ldg(col + e);
                }
            }
        } else if (aux < sBlocks + zBlocks) {
            // ---- zero g_cnt + scan flags for the NEXT call
            int zb = aux - sBlocks;
            int i = zb * blockDim.x + threadIdx.x;
            if (i < N_TOTAL / 4)
                reinterpret_cast<int4*>(g_cnt)[i] = make_int4(0, 0, 0, 0);
            if (zb == 0 && threadIdx.x < 16) {
                reinterpret_cast<int4*>(g_aggReady)[threadIdx.x] = make_int4(0, 0, 0, 0);
                reinterpret_cast<int4*>(g_blockAgg)[threadIdx.x] = make_int4(0, 0, 0, 0);
            }
        }
    } else {
        // ---- prep: X0 = fp16(d_inv[node] * E0), 8 floats per thread
        int pb = (int)b - (int)(b >> 2) - 1;     // rank among non-aux blocks
        if (pb >= pBlocks) return;
        int i = pb * blockDim.x + threadIdx.x;
        const int n8 = N_TOTAL * DIM / 8;
        if (i >= n8) return;
        float dv = __ldg(g_dinv + (i >> 3));     // 8 threads per node row
        float4 f0 = __ldg(E0 + i * 2);
        float4 f1 = __ldg(E0 + i * 2 + 1);
        uint4 h;
        h.x = h22u(__floats2half2_rn(dv * f0.x, dv * f0.y));
        h.y = h22u(__floats2half2_rn(dv * f0.z, dv * f0.w));
        h.z = h22u(__floats2half2_rn(dv * f1.x, dv * f1.y));
        h.w = h22u(__floats2half2_rn(dv * f1.z, dv * f1.w));
        reinterpret_cast<uint4*>(g_X0)[i] = h;
    }
}

// ---------------------------------------------------------------------------
// scaled-space SpMM: dst[r] = d_inv[r]^2 * sum_{c in N(r)} src[c]
// 8 threads/row, 8 dims/lane. 8-edge fp16 HADD2 tree (28 HADD2) with ONE fp32
// flush per group (8 F2F + 8 FADD) — 18% fewer issue slots than the 4-edge
// version; remainder (<=6 edges) trees accumulate in half2 and flush once.
__global__ void __launch_bounds__(256, 8)
k_spmm(const __half* __restrict__ src, __half* __restrict__ dst) {
    int t = blockIdx.x * blockDim.x + threadIdx.x;
    int r = t >> 3;
    int q = t & 7;
    if (r >= N_TOTAL) return;

    int beg  = __ldg(g_rowptr + r);
    int cnt2 = __ldg(g_rowptr + r + 1) - beg;   // padded (even)
    const int* cp = g_ecol + beg;               // beg is even -> 8B aligned
    const uint4* src4 = reinterpret_cast<const uint4*>(src);

    float2 a0[4] = {{0,0},{0,0},{0,0},{0,0}};

    int i = 0;
    for (; i + 8 <= cnt2; i += 8) {
        int2 c01 = *reinterpret_cast<const int2*>(cp + i);
        int2 c23 = *reinterpret_cast<const int2*>(cp + i + 2);
        int2 c45 = *reinterpret_cast<const int2*>(cp + i + 4);
        int2 c67 = *reinterpret_cast<const int2*>(cp + i + 6);
        uint4 h0 = __ldg(src4 + (c01.x * 8 + q));
        uint4 h1 = __ldg(src4 + (c01.y * 8 + q));
        uint4 h2 = __ldg(src4 + (c23.x * 8 + q));
        uint4 h3 = __ldg(src4 + (c23.y * 8 + q));
        uint4 h4 = __ldg(src4 + (c45.x * 8 + q));
        uint4 h5 = __ldg(src4 + (c45.y * 8 + q));
        uint4 h6 = __ldg(src4 + (c67.x * 8 + q));
        uint4 h7 = __ldg(src4 + (c67.y * 8 + q));
        __half2 tx = __hadd2(__hadd2(__hadd2(u2h2(h0.x), u2h2(h1.x)),
                                     __hadd2(u2h2(h2.x), u2h2(h3.x))),
                             __hadd2(__hadd2(u2h2(h4.x), u2h2(h5.x)),
                                     __hadd2(u2h2(h6.x), u2h2(h7.x))));
        __half2 ty = __hadd2(__hadd2(__hadd2(u2h2(h0.y), u2h2(h1.y)),
                                     __hadd2(u2h2(h2.y), u2h2(h3.y))),
                             __hadd2(__hadd2(u2h2(h4.y), u2h2(h5.y)),
                                     __hadd2(u2h2(h6.y), u2h2(h7.y))));
        __half2 tz = __hadd2(__hadd2(__hadd2(u2h2(h0.z), u2h2(h1.z)),
                                     __hadd2(u2h2(h2.z), u2h2(h3.z))),
                             __hadd2(__hadd2(u2h2(h4.z), u2h2(h5.z)),
                                     __hadd2(u2h2(h6.z), u2h2(h7.z))));
        __half2 tw = __hadd2(__hadd2(__hadd2(u2h2(h0.w), u2h2(h1.w)),
                                     __hadd2(u2h2(h2.w), u2h2(h3.w))),
                             __hadd2(__hadd2(u2h2(h4.w), u2h2(h5.w)),
                                     __hadd2(u2h2(h6.w), u2h2(h7.w))));
        float2 p;
        p = __half22float2(tx); a0[0].x += p.x; a0[0].y += p.y;
        p = __half22float2(ty); a0[1].x += p.x; a0[1].y += p.y;
        p = __half22float2(tz); a0[2].x += p.x; a0[2].y += p.y;
        p = __half22float2(tw); a0[3].x += p.x; a0[3].y += p.y;
    }

    // remainder (0, 2, 4, or 6 edges): accumulate trees in half2, flush once
    if (i < cnt2) {
        __half2 rx, ry, rz, rw;
        bool have = false;
        if (i + 4 <= cnt2) {
            int2 c01 = *reinterpret_cast<const int2*>(cp + i);
            int2 c23 = *reinterpret_cast<const int2*>(cp + i + 2);
            uint4 h0 = __ldg(src4 + (c01.x * 8 + q));
            uint4 h1 = __ldg(src4 + (c01.y * 8 + q));
            uint4 h2 = __ldg(src4 + (c23.x * 8 + q));
            uint4 h3 = __ldg(src4 + (c23.y * 8 + q));
            rx = __hadd2(__hadd2(u2h2(h0.x), u2h2(h1.x)),
                         __hadd2(u2h2(h2.x), u2h2(h3.x)));
            ry = __hadd2(__hadd2(u2h2(h0.y), u2h2(h1.y)),
                         __hadd2(u2h2(h2.y), u2h2(h3.y)));
            rz = __hadd2(__hadd2(u2h2(h0.z), u2h2(h1.z)),
                         __hadd2(u2h2(h2.z), u2h2(h3.z)));
            rw = __hadd2(__hadd2(u2h2(h0.w), u2h2(h1.w)),
                         __hadd2(u2h2(h2.w), u2h2(h3.w)));
            have = true;
            i += 4;
        }
        if (i < cnt2) {   // exactly 2 edges remain
            int2 c01 = *reinterpret_cast<const int2*>(cp + i);
            uint4 h0 = __ldg(src4 + (c01.x * 8 + q));
            uint4 h1 = __ldg(src4 + (c01.y * 8 + q));
            __half2 sx = __hadd2(u2h2(h0.x), u2h2(h1.x));
            __half2 sy = __hadd2(u2h2(h0.y), u2h2(h1.y));
            __half2 sz = __hadd2(u2h2(h0.z), u2h2(h1.z));
            __half2 sw = __hadd2(u2h2(h0.w), u2h2(h1.w));
            if (have) {
                rx = __hadd2(rx, sx); ry = __hadd2(ry, sy);
                rz = __hadd2(rz, sz); rw = __hadd2(rw, sw);
            } else {
                rx = sx; ry = sy; rz = sz; rw = sw;
            }
        }
        float2 p;
        p = __half22float2(rx); a0[0].x += p.x; a0[0].y += p.y;
        p = __half22float2(ry); a0[1].x += p.x; a0[1].y += p.y;
        p = __half22float2(rz); a0[2].x += p.x; a0[2].y += p.y;
        p = __half22float2(rw); a0[3].x += p.x; a0[3].y += p.y;
    }

    float dv = __ldg(g_dinv + r);
    float s = dv * dv;
    uint4 o;
    o.x = h22u(__floats2half2_rn(a0[0].x * s, a0[0].y * s));
    o.y = h22u(__floats2half2_rn(a0[1].x * s, a0[1].y * s));
    o.z = h22u(__floats2half2_rn(a0[2].x * s, a0[2].y * s));
    o.w = h22u(__floats2half2_rn(a0[3].x * s, a0[3].y * s));
    reinterpret_cast<uint4*>(dst)[r * 8 + q] = o;
}

// ---------------------------------------------------------------------------
// Fused layer-3 + output. For each gathered node:
//   sum3 = sum_{c in N(node)} XB[c]          (scaled-space layer-3 gather)
//   final = (E0 + (XA+XB)[node]*dpos + dinv*sum3) / 4 ;  also emit E0.
__global__ void k_out(const int* __restrict__ users, const int* __restrict__ pos,
                      const int* __restrict__ neg, const float* __restrict__ E0,
                      float* __restrict__ out) {
    int t = blockIdx.x * blockDim.x + threadIdx.x;
    if (t >= 3 * BATCH * 8) return;
    int s = t >> 15;            // BATCH*8 = 32768
    int rem = t & 32767;
    int b = rem >> 3;
    int q = rem & 7;

    int node;
    if (s == 0)      node = __ldg(users + b);
    else if (s == 1) node = N_USERS + __ldg(pos + b);
    else             node = N_USERS + __ldg(neg + b);

    int beg  = __ldg(g_rowptr + node);
    int cnt2 = __ldg(g_rowptr + node + 1) - beg;
    const int* cp = g_ecol + beg;
    const uint4* B4 = reinterpret_cast<const uint4*>(g_XB);

    float2 c0[4] = {{0,0},{0,0},{0,0},{0,0}};
    for (int i = 0; i < cnt2; i += 2) {
        int2 c01 = *reinterpret_cast<const int2*>(cp + i);
        uint4 h0 = __ldg(B4 + (c01.x * 8 + q));
        uint4 h1 = __ldg(B4 + (c01.y * 8 + q));
        __half2 tx = __hadd2(u2h2(h0.x), u2h2(h1.x));
        __half2 ty = __hadd2(u2h2(h0.y), u2h2(h1.y));
        __half2 tz = __hadd2(u2h2(h0.z), u2h2(h1.z));
        __half2 tw = __hadd2(u2h2(h0.w), u2h2(h1.w));
        float2 p;
        p = __half22float2(tx); c0[0].x += p.x; c0[0].y += p.y;
        p = __half22float2(ty); c0[1].x += p.x; c0[1].y += p.y;
        p = __half22float2(tz); c0[2].x += p.x; c0[2].y += p.y;
        p = __half22float2(tw); c0[3].x += p.x; c0[3].y += p.y;
    }

    float dv = __ldg(g_dinv + node);
    float dp = __ldg(g_dpos + node);

    int off4 = node * 8 + q;
    uint4 ha = __ldg(reinterpret_cast<const uint4*>(g_XA) + off4);
    uint4 hb = __ldg(B4 + off4);
    size_t offf = (size_t)node * DIM + q * 8;
    float4 e00 = __ldg(reinterpret_cast<const float4*>(E0 + offf));
    float4 e01v = __ldg(reinterpret_cast<const float4*>(E0 + offf + 4));

    float2 pa, pb;
    float outv[8];
    pa = __half22float2(u2h2(ha.x)); pb = __half22float2(u2h2(hb.x));
    outv[0] = (e00.x + (pa.x + pb.x) * dp + dv * c0[0].x) * 0.25f;
    outv[1] = (e00.y + (pa.y + pb.y) * dp + dv * c0[0].y) * 0.25f;
    pa = __half22float2(u2h2(ha.y)); pb = __half22float2(u2h2(hb.y));
    outv[2] = (e00.z + (pa.x + pb.x) * dp + dv * c0[1].x) * 0.25f;
    outv[3] = (e00.w + (pa.y + pb.y) * dp + dv * c0[1].y) * 0.25f;
    pa = __half22float2(u2h2(ha.z)); pb = __half22float2(u2h2(hb.z));
    outv[4] = (e01v.x + (pa.x + pb.x) * dp + dv * c0[2].x) * 0.25f;
    outv[5] = (e01v.y + (pa.y + pb.y) * dp + dv * c0[2].y) * 0.25f;
    pa = __half22float2(u2h2(ha.w)); pb = __half22float2(u2h2(hb.w));
    outv[6] = (e01v.z + (pa.x + pb.x) * dp + dv * c0[3].x) * 0.25f;
    outv[7] = (e01v.w + (pa.y + pb.y) * dp + dv * c0[3].y) * 0.25f;

    const int S = BATCH * DIM;
    int o = b * DIM + q * 8;
    float4* op = reinterpret_cast<float4*>(out + (size_t)s * S + o);
    op[0] = make_float4(outv[0], outv[1], outv[2], outv[3]);
    op[1] = make_float4(outv[4], outv[5], outv[6], outv[7]);
    float4* oe = reinterpret_cast<float4*>(out + (size_t)(s + 3) * S + o);
    oe[0] = e00;
    oe[1] = e01v;
}

extern "C" void kernel_launch(void* const* d_in, const int* in_sizes, int n_in,
                              void* d_out, int out_size) {
    const int*   users = (const int*)d_in[0];
    const int*   pos   = (const int*)d_in[1];
    const int*   neg   = (const int*)d_in[2];
    const float* E0    = (const float*)d_in[3];
    const int*   row   = (const int*)d_in[4];
    const int*   col   = (const int*)d_in[5];
    const int    nnz   = in_sizes[4];

    __half *X0, *XA, *XB;
    cudaGetSymbolAddress((void**)&X0, g_X0);
    cudaGetSymbolAddress((void**)&XA, g_XA);
    cudaGetSymbolAddress((void**)&XB, g_XB);

    const int TB = 256;

    // CSR build + normalizers (counters zeroed by previous call / load-time init)
    int quads = (nnz + 3) / 4;
    k_hist<<<(quads + TB - 1) / TB, TB>>>(row, nnz);
    k_scan<<<NB, 1024>>>();

    // fused scatter + prep + re-zero, interleaved for intra-wave overlap
    const int n8 = N_TOTAL * DIM / 8;
    int sBlocks = (quads + TB - 1) / TB;
    int zBlocks = (N_TOTAL / 4 + TB - 1) / TB;
    int pBlocks = (n8 + TB - 1) / TB;
    int auxBlocks = sBlocks + zBlocks;
    int total = (pBlocks * 4 + 2) / 3;          // prep needs 3/4 of the grid
    if (total < auxBlocks * 4) total = auxBlocks * 4;
    total = (total + 3) & ~3;
    k_prep_scatter<<<total, TB>>>((const float4*)E0, row, col,
                                  nnz, sBlocks, zBlocks, pBlocks);

    // 2 scaled-space propagation layers
    const int spmmGrid = (N_TOTAL * 8 + TB - 1) / TB;
    k_spmm<<<spmmGrid, TB>>>(X0, XA);   // XA = Dinv2 * (A @ X0)
    k_spmm<<<spmmGrid, TB>>>(XA, XB);   // XB = Dinv2 * (A @ XA)

    // fused layer 3 + gather
    int outThreads = 3 * BATCH * 8;
    k_out<<<(outThreads + TB - 1) / TB, TB>>>(users, pos, neg, E0, (float*)d_out);
}

// round 14
// speedup vs baseline: 1.1238x; 1.1238x over previous
#include <cuda_runtime.h>
#include <cuda_fp16.h>

#define N_USERS  100000
#define N_TOTAL  150000
#define DIM      64
#define BATCH    4096
#define NNZ_MAX  1400000     // 1.2M edges + up to 150k pad slots

#define SCAN_TILE 4096                                  // 1024 threads x 4 items
#define NB ((N_TOTAL + SCAN_TILE - 1) / SCAN_TILE)      // 37 blocks (all resident)

// Scaled-space embeddings X_k = d_inv ⊙ E_k, fp16, with one extra zero row
// (index N_TOTAL) used as the gather target of pad edges. All __device__
// globals are zero-initialized at module load; the sentinel rows are never
// written, so they stay zero. g_cnt and the scan flags are re-zeroed each call
// by the aux lane of k_prep_scatter (for the NEXT call).
__device__ __half g_X0[(N_TOTAL + 1) * DIM];
__device__ __half g_XA[(N_TOTAL + 1) * DIM];
__device__ __half g_XB[(N_TOTAL + 1) * DIM];
__device__ float g_dinv[N_TOTAL];        // (deg+1e-9)^-0.5
__device__ float g_dpos[N_TOTAL];        // (deg+1e-9)^+0.5  (to unscale)
__device__ int   g_cnt[N_TOTAL];         // true row degree (zeroed for next call)
__device__ int   g_rowptr[N_TOTAL + 1];  // padded exclusive scan (+ total at end)
__device__ int   g_rank[NNZ_MAX];        // intra-row rank per edge (from hist)
__device__ int   g_ecol[NNZ_MAX];        // CSR column indices; pad slots = N_TOTAL
__device__ int   g_blockAgg[64];
__device__ int   g_aggReady[64];

__device__ __forceinline__ __half2 u2h2(unsigned u) {
    __half2 h; *reinterpret_cast<unsigned*>(&h) = u; return h;
}
__device__ __forceinline__ unsigned h22u(__half2 h) {
    return *reinterpret_cast<unsigned*>(&h);
}

// ---------------------------------------------------------------------------
// histogram of row ids, capturing each edge's intra-row rank (4 edges/thread)
__global__ void k_hist(const int* __restrict__ row, int nnz) {
    int t = blockIdx.x * blockDim.x + threadIdx.x;
    int base = t * 4;
    if (base + 4 <= nnz) {
        int4 r = __ldg(reinterpret_cast<const int4*>(row + base));
        int4 k;
        k.x = atomicAdd(&g_cnt[r.x], 1);
        k.y = atomicAdd(&g_cnt[r.y], 1);
        k.z = atomicAdd(&g_cnt[r.z], 1);
        k.w = atomicAdd(&g_cnt[r.w], 1);
        *reinterpret_cast<int4*>(g_rank + base) = k;
    } else {
        for (int e = base; e < nnz; e++)
            g_rank[e] = atomicAdd(&g_cnt[__ldg(row + e)], 1);
    }
}

// single-pass exclusive scan of padded counts -> rowptr (incl. total at
// rowptr[N_TOTAL]); derives degree normalizers; writes pad-edge sentinels.
__global__ void k_scan() {
    __shared__ int warpsum[32];
    __shared__ int s_aggs[64];
    __shared__ int s_prev;
    int tid  = threadIdx.x;
    int lane = tid & 31, wid = tid >> 5;
    int base = blockIdx.x * SCAN_TILE + tid * 4;

    int cc[4], cp[4];
#pragma unroll
    for (int k = 0; k < 4; k++) {
        int idx = base + k;
        cc[k] = (idx < N_TOTAL) ? g_cnt[idx] : 0;
        cp[k] = (cc[k] + 1) & ~1;                 // padded to even
    }
    int t = cp[0] + cp[1] + cp[2] + cp[3];

    int x = t;
#pragma unroll
    for (int o = 1; o < 32; o <<= 1) {
        int y = __shfl_up_sync(0xffffffffu, x, o);
        if (lane >= o) x += y;
    }
    if (lane == 31) warpsum[wid] = x;
    __syncthreads();
    if (wid == 0) {
        int v = warpsum[lane];
#pragma unroll
        for (int o = 1; o < 32; o <<= 1) {
            int y = __shfl_up_sync(0xffffffffu, v, o);
            if (lane >= o) v += y;
        }
        warpsum[lane] = v;
    }
    __syncthreads();

    if (tid == 0) {
        g_blockAgg[blockIdx.x] = warpsum[31];
        __threadfence();
        atomicExch(&g_aggReady[blockIdx.x], 1);
    }
    if (tid < blockIdx.x) {
        while (atomicAdd(&g_aggReady[tid], 0) == 0) { }
        __threadfence();
        s_aggs[tid] = g_blockAgg[tid];
    }
    __syncthreads();
    if (tid == 0) {
        int p = 0;
        for (int j = 0; j < blockIdx.x; j++) p += s_aggs[j];
        s_prev = p;
    }
    __syncthreads();

    int woff = (wid == 0) ? 0 : warpsum[wid - 1];
    int run = s_prev + woff + (x - t);
#pragma unroll
    for (int k = 0; k < 4; k++) {
        int idx = base + k;
        if (idx < N_TOTAL) {
            g_rowptr[idx] = run;
            float degf = (float)cc[k] + 1e-9f;
            g_dinv[idx] = rsqrtf(degf);
            g_dpos[idx] = sqrtf(degf);
            if (cc[k] & 1) g_ecol[run + cc[k]] = N_TOTAL;   // pad -> zero row
            run += cp[k];
            if (idx == N_TOTAL - 1) g_rowptr[N_TOTAL] = run;  // total
        }
    }
}

// ---------------------------------------------------------------------------
// Fused scatter + prep + counter-rezero, blocks interleaved by modulo so every
// scheduling wave mixes L2-latency-bound scatter with DRAM-streaming prep.
__global__ void k_prep_scatter(const float4* __restrict__ E0,
                               const int* __restrict__ row,
                               const int* __restrict__ col,
                               int nnz, int sBlocks, int zBlocks, int pBlocks) {
    unsigned b = blockIdx.x;
    if ((b & 3u) == 0u) {
        int aux = b >> 2;
        if (aux < sBlocks) {
            // ---- scatter: 4 edges/thread, slot = rowptr[row] + rank[edge]
            int t = aux * blockDim.x + threadIdx.x;
            int base = t * 4;
            if (base + 4 <= nnz) {
                int4 r = __ldg(reinterpret_cast<const int4*>(row + base));
                int4 c = __ldg(reinterpret_cast<const int4*>(col + base));
                int4 k = *reinterpret_cast<const int4*>(g_rank + base);
                g_ecol[__ldg(g_rowptr + r.x) + k.x] = c.x;
                g_ecol[__ldg(g_rowptr + r.y) + k.y] = c.y;
                g_ecol[__ldg(g_rowptr + r.z) + k.z] = c.z;
                g_ecol[__ldg(g_rowptr + r.w) + k.w] = c.w;
            } else {
                for (int e = base; e < nnz; e++) {
                    int rr = __ldg(row + e);
                    g_ecol[__ldg(g_rowptr + rr) + g_rank[e]] = __ldg(col + e);
                }
            }
        } else if (aux < sBlocks + zBlocks) {
            // ---- zero g_cnt + scan flags for the NEXT call
            int zb = aux - sBlocks;
            int i = zb * blockDim.x + threadIdx.x;
            if (i < N_TOTAL / 4)
                reinterpret_cast<int4*>(g_cnt)[i] = make_int4(0, 0, 0, 0);
            if (zb == 0 && threadIdx.x < 16) {
                reinterpret_cast<int4*>(g_aggReady)[threadIdx.x] = make_int4(0, 0, 0, 0);
                reinterpret_cast<int4*>(g_blockAgg)[threadIdx.x] = make_int4(0, 0, 0, 0);
            }
        }
    } else {
        // ---- prep: X0 = fp16(d_inv[node] * E0), 8 floats per thread
        int pb = (int)b - (int)(b >> 2) - 1;     // rank among non-aux blocks
        if (pb >= pBlocks) return;
        int i = pb * blockDim.x + threadIdx.x;
        const int n8 = N_TOTAL * DIM / 8;
        if (i >= n8) return;
        float dv = __ldg(g_dinv + (i >> 3));     // 8 threads per node row
        float4 f0 = __ldg(E0 + i * 2);
        float4 f1 = __ldg(E0 + i * 2 + 1);
        uint4 h;
        h.x = h22u(__floats2half2_rn(dv * f0.x, dv * f0.y));
        h.y = h22u(__floats2half2_rn(dv * f0.z, dv * f0.w));
        h.z = h22u(__floats2half2_rn(dv * f1.x, dv * f1.y));
        h.w = h22u(__floats2half2_rn(dv * f1.z, dv * f1.w));
        reinterpret_cast<uint4*>(g_X0)[i] = h;
    }
}

// ---------------------------------------------------------------------------
// scaled-space SpMM: dst[r] = d_inv[r]^2 * sum_{c in N(r)} src[c]
// 8 threads/row, 8 dims/lane. 4-edge HADD2 tree + single fp32 flush per group
// (the 8-edge variant spilled under the 32-reg cap — reverted).
// __launch_bounds__(256, 8) caps regs at 32 -> 8 blocks/SM.
__global__ void __launch_bounds__(256, 8)
k_spmm(const __half* __restrict__ src, __half* __restrict__ dst) {
    int t = blockIdx.x * blockDim.x + threadIdx.x;
    int r = t >> 3;
    int q = t & 7;
    if (r >= N_TOTAL) return;

    int beg  = __ldg(g_rowptr + r);
    int cnt2 = __ldg(g_rowptr + r + 1) - beg;   // padded (even)
    float dv = __ldg(g_dinv + r);               // hoisted: hides under the loop
    const int* cp = g_ecol + beg;               // beg is even -> 8B aligned
    const uint4* src4 = reinterpret_cast<const uint4*>(src);

    float2 a0[4] = {{0,0},{0,0},{0,0},{0,0}};

    int i = 0;
    for (; i + 4 <= cnt2; i += 4) {
        int2 c01 = __ldg(reinterpret_cast<const int2*>(cp + i));
        int2 c23 = __ldg(reinterpret_cast<const int2*>(cp + i + 2));
        uint4 h0 = __ldg(src4 + (c01.x * 8 + q));
        uint4 h1 = __ldg(src4 + (c01.y * 8 + q));
        uint4 h2 = __ldg(src4 + (c23.x * 8 + q));
        uint4 h3 = __ldg(src4 + (c23.y * 8 + q));
        __half2 tx = __hadd2(__hadd2(u2h2(h0.x), u2h2(h1.x)),
                             __hadd2(u2h2(h2.x), u2h2(h3.x)));
        __half2 ty = __hadd2(__hadd2(u2h2(h0.y), u2h2(h1.y)),
                             __hadd2(u2h2(h2.y), u2h2(h3.y)));
        __half2 tz = __hadd2(__hadd2(u2h2(h0.z), u2h2(h1.z)),
                             __hadd2(u2h2(h2.z), u2h2(h3.z)));
        __half2 tw = __hadd2(__hadd2(u2h2(h0.w), u2h2(h1.w)),
                             __hadd2(u2h2(h2.w), u2h2(h3.w)));
        float2 p;
        p = __half22float2(tx); a0[0].x += p.x; a0[0].y += p.y;
        p = __half22float2(ty); a0[1].x += p.x; a0[1].y += p.y;
        p = __half22float2(tz); a0[2].x += p.x; a0[2].y += p.y;
        p = __half22float2(tw); a0[3].x += p.x; a0[3].y += p.y;
    }
    if (i < cnt2) {   // exactly 2 edges remain (cnt2 is even)
        int2 c01 = __ldg(reinterpret_cast<const int2*>(cp + i));
        uint4 h0 = __ldg(src4 + (c01.x * 8 + q));
        uint4 h1 = __ldg(src4 + (c01.y * 8 + q));
        __half2 tx = __hadd2(u2h2(h0.x), u2h2(h1.x));
        __half2 ty = __hadd2(u2h2(h0.y), u2h2(h1.y));
        __half2 tz = __hadd2(u2h2(h0.z), u2h2(h1.z));
        __half2 tw = __hadd2(u2h2(h0.w), u2h2(h1.w));
        float2 p;
        p = __half22float2(tx); a0[0].x += p.x; a0[0].y += p.y;
        p = __half22float2(ty); a0[1].x += p.x; a0[1].y += p.y;
        p = __half22float2(tz); a0[2].x += p.x; a0[2].y += p.y;
        p = __half22float2(tw); a0[3].x += p.x; a0[3].y += p.y;
    }

    float s = dv * dv;
    uint4 o;
    o.x = h22u(__floats2half2_rn(a0[0].x * s, a0[0].y * s));
    o.y = h22u(__floats2half2_rn(a0[1].x * s, a0[1].y * s));
    o.z = h22u(__floats2half2_rn(a0[2].x * s, a0[2].y * s));
    o.w = h22u(__floats2half2_rn(a0[3].x * s, a0[3].y * s));
    reinterpret_cast<uint4*>(dst)[r * 8 + q] = o;
}

// ---------------------------------------------------------------------------
// Fused layer-3 + output. For each gathered node:
//   sum3 = sum_{c in N(node)} XB[c]          (scaled-space layer-3 gather)
//   final = (E0 + (XA+XB)[node]*dpos + dinv*sum3) / 4 ;  also emit E0.
__global__ void k_out(const int* __restrict__ users, const int* __restrict__ pos,
                      const int* __restrict__ neg, const float* __restrict__ E0,
                      float* __restrict__ out) {
    int t = blockIdx.x * blockDim.x + threadIdx.x;
    if (t >= 3 * BATCH * 8) return;
    int s = t >> 15;            // BATCH*8 = 32768
    int rem = t & 32767;
    int b = rem >> 3;
    int q = rem & 7;

    int node;
    if (s == 0)      node = __ldg(users + b);
    else if (s == 1) node = N_USERS + __ldg(pos + b);
    else             node = N_USERS + __ldg(neg + b);

    int beg  = __ldg(g_rowptr + node);
    int cnt2 = __ldg(g_rowptr + node + 1) - beg;
    const int* cp = g_ecol + beg;
    const uint4* B4 = reinterpret_cast<const uint4*>(g_XB);

    float2 c0[4] = {{0,0},{0,0},{0,0},{0,0}};
    for (int i = 0; i < cnt2; i += 2) {
        int2 c01 = __ldg(reinterpret_cast<const int2*>(cp + i));
        uint4 h0 = __ldg(B4 + (c01.x * 8 + q));
        uint4 h1 = __ldg(B4 + (c01.y * 8 + q));
        __half2 tx = __hadd2(u2h2(h0.x), u2h2(h1.x));
        __half2 ty = __hadd2(u2h2(h0.y), u2h2(h1.y));
        __half2 tz = __hadd2(u2h2(h0.z), u2h2(h1.z));
        __half2 tw = __hadd2(u2h2(h0.w), u2h2(h1.w));
        float2 p;
        p = __half22float2(tx); c0[0].x += p.x; c0[0].y += p.y;
        p = __half22float2(ty); c0[1].x += p.x; c0[1].y += p.y;
        p = __half22float2(tz); c0[2].x += p.x; c0[2].y += p.y;
        p = __half22float2(tw); c0[3].x += p.x; c0[3].y += p.y;
    }

    float dv = __ldg(g_dinv + node);
    float dp = __ldg(g_dpos + node);

    int off4 = node * 8 + q;
    uint4 ha = __ldg(reinterpret_cast<const uint4*>(g_XA) + off4);
    uint4 hb = __ldg(B4 + off4);
    size_t offf = (size_t)node * DIM + q * 8;
    float4 e00 = __ldg(reinterpret_cast<const float4*>(E0 + offf));
    float4 e01v = __ldg(reinterpret_cast<const float4*>(E0 + offf + 4));

    float2 pa, pb;
    float outv[8];
    pa = __half22float2(u2h2(ha.x)); pb = __half22float2(u2h2(hb.x));
    outv[0] = (e00.x + (pa.x + pb.x) * dp + dv * c0[0].x) * 0.25f;
    outv[1] = (e00.y + (pa.y + pb.y) * dp + dv * c0[0].y) * 0.25f;
    pa = __half22float2(u2h2(ha.y)); pb = __half22float2(u2h2(hb.y));
    outv[2] = (e00.z + (pa.x + pb.x) * dp + dv * c0[1].x) * 0.25f;
    outv[3] = (e00.w + (pa.y + pb.y) * dp + dv * c0[1].y) * 0.25f;
    pa = __half22float2(u2h2(ha.z)); pb = __half22float2(u2h2(hb.z));
    outv[4] = (e01v.x + (pa.x + pb.x) * dp + dv * c0[2].x) * 0.25f;
    outv[5] = (e01v.y + (pa.y + pb.y) * dp + dv * c0[2].y) * 0.25f;
    pa = __half22float2(u2h2(ha.w)); pb = __half22float2(u2h2(hb.w));
    outv[6] = (e01v.z + (pa.x + pb.x) * dp + dv * c0[3].x) * 0.25f;
    outv[7] = (e01v.w + (pa.y + pb.y) * dp + dv * c0[3].y) * 0.25f;

    const int S = BATCH * DIM;
    int o = b * DIM + q * 8;
    float4* op = reinterpret_cast<float4*>(out + (size_t)s * S + o);
    op[0] = make_float4(outv[0], outv[1], outv[2], outv[3]);
    op[1] = make_float4(outv[4], outv[5], outv[6], outv[7]);
    float4* oe = reinterpret_cast<float4*>(out + (size_t)(s + 3) * S + o);
    oe[0] = e00;
    oe[1] = e01v;
}

extern "C" void kernel_launch(void* const* d_in, const int* in_sizes, int n_in,
                              void* d_out, int out_size) {
    const int*   users = (const int*)d_in[0];
    const int*   pos   = (const int*)d_in[1];
    const int*   neg   = (const int*)d_in[2];
    const float* E0    = (const float*)d_in[3];
    const int*   row   = (const int*)d_in[4];
    const int*   col   = (const int*)d_in[5];
    const int    nnz   = in_sizes[4];

    __half *X0, *XA, *XB;
    cudaGetSymbolAddress((void**)&X0, g_X0);
    cudaGetSymbolAddress((void**)&XA, g_XA);
    cudaGetSymbolAddress((void**)&XB, g_XB);

    const int TB = 256;

    // CSR build + normalizers (counters zeroed by previous call / load-time init)
    int quads = (nnz + 3) / 4;
    k_hist<<<(quads + TB - 1) / TB, TB>>>(row, nnz);
    k_scan<<<NB, 1024>>>();

    // fused scatter + prep + re-zero, interleaved for intra-wave overlap
    const int n8 = N_TOTAL * DIM / 8;
    int sBlocks = (quads + TB - 1) / TB;
    int zBlocks = (N_TOTAL / 4 + TB - 1) / TB;
    int pBlocks = (n8 + TB - 1) / TB;
    int auxBlocks = sBlocks + zBlocks;
    int total = (pBlocks * 4 + 2) / 3;          // prep needs 3/4 of the grid
    if (total < auxBlocks * 4) total = auxBlocks * 4;
    total = (total + 3) & ~3;
    k_prep_scatter<<<total, TB>>>((const float4*)E0, row, col,
                                  nnz, sBlocks, zBlocks, pBlocks);

    // 2 scaled-space propagation layers
    const int spmmGrid = (N_TOTAL * 8 + TB - 1) / TB;
    k_spmm<<<spmmGrid, TB>>>(X0, XA);   // XA = Dinv2 * (A @ X0)
    k_spmm<<<spmmGrid, TB>>>(XA, XB);   // XB = Dinv2 * (A @ XA)

    // fused layer 3 + gather
    int outThreads = 3 * BATCH * 8;
    k_out<<<(outThreads + TB - 1) / TB, TB>>>(users, pos, neg, E0, (float*)d_out);
}

// round 15
// speedup vs baseline: 1.1505x; 1.0237x over previous
#include <cuda_runtime.h>
#include <cuda_fp16.h>

#define N_USERS  100000
#define N_TOTAL  150000
#define DIM      64
#define BATCH    4096
#define NNZ_MAX  1400000     // 1.2M edges + up to 150k pad slots

#define SCAN_TILE 4096                                  // 1024 threads x 4 items
#define NB ((N_TOTAL + SCAN_TILE - 1) / SCAN_TILE)      // 37 blocks (all resident)

// Scaled-space embeddings X_k = d_inv ⊙ E_k, fp16, with one extra zero row
// (index N_TOTAL) used as the gather target of pad edges. All __device__
// globals are zero-initialized at module load; the sentinel rows are never
// written, so they stay zero. g_cnt and the scan flags are re-zeroed each call
// by the aux lane of k_prep_scatter (for the NEXT call).
__device__ __half g_X0[(N_TOTAL + 1) * DIM];
__device__ __half g_XA[(N_TOTAL + 1) * DIM];
__device__ __half g_XB[(N_TOTAL + 1) * DIM];
__device__ float g_dinv[N_TOTAL];        // (deg+1e-9)^-0.5
__device__ float g_dpos[N_TOTAL];        // (deg+1e-9)^+0.5  (to unscale)
__device__ int   g_cnt[N_TOTAL];         // true row degree (zeroed for next call)
__device__ int   g_rowptr[N_TOTAL + 1];  // padded exclusive scan (+ total at end)
__device__ int   g_rank[NNZ_MAX];        // intra-row rank per edge (from hist)
__device__ int   g_ecol[NNZ_MAX];        // CSR column indices; pad slots = N_TOTAL
__device__ int   g_blockAgg[64];
__device__ int   g_aggReady[64];

__device__ __forceinline__ __half2 u2h2(unsigned u) {
    __half2 h; *reinterpret_cast<unsigned*>(&h) = u; return h;
}
__device__ __forceinline__ unsigned h22u(__half2 h) {
    return *reinterpret_cast<unsigned*>(&h);
}

// ---------------------------------------------------------------------------
// histogram of row ids, capturing each edge's intra-row rank.
// 2 edges/thread: atomic-with-return is the bottleneck; a larger warp pool
// hides its ~318cyc latency better than per-thread MLP (scatter lesson R4/R7).
__global__ void k_hist(const int* __restrict__ row, int nnz) {
    int t = blockIdx.x * blockDim.x + threadIdx.x;
    int base = t * 2;
    if (base + 2 <= nnz) {
        int2 r = __ldg(reinterpret_cast<const int2*>(row + base));
        int2 k;
        k.x = atomicAdd(&g_cnt[r.x], 1);
        k.y = atomicAdd(&g_cnt[r.y], 1);
        *reinterpret_cast<int2*>(g_rank + base) = k;
    } else if (base < nnz) {
        g_rank[base] = atomicAdd(&g_cnt[__ldg(row + base)], 1);
    }
}

// single-pass exclusive scan of padded counts -> rowptr (incl. total at
// rowptr[N_TOTAL]); derives degree normalizers; writes pad-edge sentinels.
__global__ void k_scan() {
    __shared__ int warpsum[32];
    __shared__ int s_aggs[64];
    __shared__ int s_prev;
    int tid  = threadIdx.x;
    int lane = tid & 31, wid = tid >> 5;
    int base = blockIdx.x * SCAN_TILE + tid * 4;

    int cc[4], cp[4];
#pragma unroll
    for (int k = 0; k < 4; k++) {
        int idx = base + k;
        cc[k] = (idx < N_TOTAL) ? g_cnt[idx] : 0;
        cp[k] = (cc[k] + 1) & ~1;                 // padded to even
    }
    int t = cp[0] + cp[1] + cp[2] + cp[3];

    int x = t;
#pragma unroll
    for (int o = 1; o < 32; o <<= 1) {
        int y = __shfl_up_sync(0xffffffffu, x, o);
        if (lane >= o) x += y;
    }
    if (lane == 31) warpsum[wid] = x;
    __syncthreads();
    if (wid == 0) {
        int v = warpsum[lane];
#pragma unroll
        for (int o = 1; o < 32; o <<= 1) {
            int y = __shfl_up_sync(0xffffffffu, v, o);
            if (lane >= o) v += y;
        }
        warpsum[lane] = v;
    }
    __syncthreads();

    if (tid == 0) {
        g_blockAgg[blockIdx.x] = warpsum[31];
        __threadfence();
        atomicExch(&g_aggReady[blockIdx.x], 1);
    }
    if (tid < blockIdx.x) {
        while (atomicAdd(&g_aggReady[tid], 0) == 0) { }
        __threadfence();
        s_aggs[tid] = g_blockAgg[tid];
    }
    __syncthreads();
    if (tid == 0) {
        int p = 0;
        for (int j = 0; j < blockIdx.x; j++) p += s_aggs[j];
        s_prev = p;
    }
    __syncthreads();

    int woff = (wid == 0) ? 0 : warpsum[wid - 1];
    int run = s_prev + woff + (x - t);
#pragma unroll
    for (int k = 0; k < 4; k++) {
        int idx = base + k;
        if (idx < N_TOTAL) {
            g_rowptr[idx] = run;
            float degf = (float)cc[k] + 1e-9f;
            g_dinv[idx] = rsqrtf(degf);
            g_dpos[idx] = sqrtf(degf);
            if (cc[k] & 1) g_ecol[run + cc[k]] = N_TOTAL;   // pad -> zero row
            run += cp[k];
            if (idx == N_TOTAL - 1) g_rowptr[N_TOTAL] = run;  // total
        }
    }
}

// ---------------------------------------------------------------------------
// Fused scatter + prep + counter-rezero, blocks interleaved by modulo so every
// scheduling wave mixes L2-latency-bound scatter with DRAM-streaming prep.
__global__ void k_prep_scatter(const float4* __restrict__ E0,
                               const int* __restrict__ row,
                               const int* __restrict__ col,
                               int nnz, int sBlocks, int zBlocks, int pBlocks) {
    unsigned b = blockIdx.x;
    if ((b & 3u) == 0u) {
        int aux = b >> 2;
        if (aux < sBlocks) {
            // ---- scatter: 4 edges/thread, slot = rowptr[row] + rank[edge]
            int t = aux * blockDim.x + threadIdx.x;
            int base = t * 4;
            if (base + 4 <= nnz) {
                int4 r = __ldg(reinterpret_cast<const int4*>(row + base));
                int4 c = __ldg(reinterpret_cast<const int4*>(col + base));
                int4 k = *reinterpret_cast<const int4*>(g_rank + base);
                g_ecol[__ldg(g_rowptr + r.x) + k.x] = c.x;
                g_ecol[__ldg(g_rowptr + r.y) + k.y] = c.y;
                g_ecol[__ldg(g_rowptr + r.z) + k.z] = c.z;
                g_ecol[__ldg(g_rowptr + r.w) + k.w] = c.w;
            } else {
                for (int e = base; e < nnz; e++) {
                    int rr = __ldg(row + e);
                    g_ecol[__ldg(g_rowptr + rr) + g_rank[e]] = __ldg(col + e);
                }
            }
        } else if (aux < sBlocks + zBlocks) {
            // ---- zero g_cnt + scan flags for the NEXT call
            int zb = aux - sBlocks;
            int i = zb * blockDim.x + threadIdx.x;
            if (i < N_TOTAL / 4)
                reinterpret_cast<int4*>(g_cnt)[i] = make_int4(0, 0, 0, 0);
            if (zb == 0 && threadIdx.x < 16) {
                reinterpret_cast<int4*>(g_aggReady)[threadIdx.x] = make_int4(0, 0, 0, 0);
                reinterpret_cast<int4*>(g_blockAgg)[threadIdx.x] = make_int4(0, 0, 0, 0);
            }
        }
    } else {
        // ---- prep: X0 = fp16(d_inv[node] * E0), 8 floats per thread
        int pb = (int)b - (int)(b >> 2) - 1;     // rank among non-aux blocks
        if (pb >= pBlocks) return;
        int i = pb * blockDim.x + threadIdx.x;
        const int n8 = N_TOTAL * DIM / 8;
        if (i >= n8) return;
        float dv = __ldg(g_dinv + (i >> 3));     // 8 threads per node row
        float4 f0 = __ldg(E0 + i * 2);
        float4 f1 = __ldg(E0 + i * 2 + 1);
        uint4 h;
        h.x = h22u(__floats2half2_rn(dv * f0.x, dv * f0.y));
        h.y = h22u(__floats2half2_rn(dv * f0.z, dv * f0.w));
        h.z = h22u(__floats2half2_rn(dv * f1.x, dv * f1.y));
        h.w = h22u(__floats2half2_rn(dv * f1.z, dv * f1.w));
        reinterpret_cast<uint4*>(g_X0)[i] = h;
    }
}

// ---------------------------------------------------------------------------
// scaled-space SpMM: dst[r] = d_inv[r]^2 * sum_{c in N(r)} src[c]
// 8 threads/row, 8 dims/lane. 4-edge HADD2 tree + single fp32 flush per group.
// EXACT round-12 codegen: dinv loaded after the loop, plain-deref index loads
// (the hoist/ldg variants spilled under the 32-reg cap — verified regressions).
__global__ void __launch_bounds__(256, 8)
k_spmm(const __half* __restrict__ src, __half* __restrict__ dst) {
    int t = blockIdx.x * blockDim.x + threadIdx.x;
    int r = t >> 3;
    int q = t & 7;
    if (r >= N_TOTAL) return;

    int beg  = __ldg(g_rowptr + r);
    int cnt2 = __ldg(g_rowptr + r + 1) - beg;   // padded (even)
    const int* cp = g_ecol + beg;               // beg is even -> 8B aligned
    const uint4* src4 = reinterpret_cast<const uint4*>(src);

    float2 a0[4] = {{0,0},{0,0},{0,0},{0,0}};

    int i = 0;
    for (; i + 4 <= cnt2; i += 4) {
        int2 c01 = *reinterpret_cast<const int2*>(cp + i);
        int2 c23 = *reinterpret_cast<const int2*>(cp + i + 2);
        uint4 h0 = __ldg(src4 + (c01.x * 8 + q));
        uint4 h1 = __ldg(src4 + (c01.y * 8 + q));
        uint4 h2 = __ldg(src4 + (c23.x * 8 + q));
        uint4 h3 = __ldg(src4 + (c23.y * 8 + q));
        __half2 tx = __hadd2(__hadd2(u2h2(h0.x), u2h2(h1.x)),
                             __hadd2(u2h2(h2.x), u2h2(h3.x)));
        __half2 ty = __hadd2(__hadd2(u2h2(h0.y), u2h2(h1.y)),
                             __hadd2(u2h2(h2.y), u2h2(h3.y)));
        __half2 tz = __hadd2(__hadd2(u2h2(h0.z), u2h2(h1.z)),
                             __hadd2(u2h2(h2.z), u2h2(h3.z)));
        __half2 tw = __hadd2(__hadd2(u2h2(h0.w), u2h2(h1.w)),
                             __hadd2(u2h2(h2.w), u2h2(h3.w)));
        float2 p;
        p = __half22float2(tx); a0[0].x += p.x; a0[0].y += p.y;
        p = __half22float2(ty); a0[1].x += p.x; a0[1].y += p.y;
        p = __half22float2(tz); a0[2].x += p.x; a0[2].y += p.y;
        p = __half22float2(tw); a0[3].x += p.x; a0[3].y += p.y;
    }
    if (i < cnt2) {   // exactly 2 edges remain (cnt2 is even)
        int2 c01 = *reinterpret_cast<const int2*>(cp + i);
        uint4 h0 = __ldg(src4 + (c01.x * 8 + q));
        uint4 h1 = __ldg(src4 + (c01.y * 8 + q));
        __half2 tx = __hadd2(u2h2(h0.x), u2h2(h1.x));
        __half2 ty = __hadd2(u2h2(h0.y), u2h2(h1.y));
        __half2 tz = __hadd2(u2h2(h0.z), u2h2(h1.z));
        __half2 tw = __hadd2(u2h2(h0.w), u2h2(h1.w));
        float2 p;
        p = __half22float2(tx); a0[0].x += p.x; a0[0].y += p.y;
        p = __half22float2(ty); a0[1].x += p.x; a0[1].y += p.y;
        p = __half22float2(tz); a0[2].x += p.x; a0[2].y += p.y;
        p = __half22float2(tw); a0[3].x += p.x; a0[3].y += p.y;
    }

    float dv = __ldg(g_dinv + r);
    float s = dv * dv;
    uint4 o;
    o.x = h22u(__floats2half2_rn(a0[0].x * s, a0[0].y * s));
    o.y = h22u(__floats2half2_rn(a0[1].x * s, a0[1].y * s));
    o.z = h22u(__floats2half2_rn(a0[2].x * s, a0[2].y * s));
    o.w = h22u(__floats2half2_rn(a0[3].x * s, a0[3].y * s));
    reinterpret_cast<uint4*>(dst)[r * 8 + q] = o;
}

// ---------------------------------------------------------------------------
// Fused layer-3 + output. For each gathered node:
//   sum3 = sum_{c in N(node)} XB[c]          (scaled-space layer-3 gather)
//   final = (E0 + (XA+XB)[node]*dpos + dinv*sum3) / 4 ;  also emit E0.
__global__ void k_out(const int* __restrict__ users, const int* __restrict__ pos,
                      const int* __restrict__ neg, const float* __restrict__ E0,
                      float* __restrict__ out) {
    int t = blockIdx.x * blockDim.x + threadIdx.x;
    if (t >= 3 * BATCH * 8) return;
    int s = t >> 15;            // BATCH*8 = 32768
    int rem = t & 32767;
    int b = rem >> 3;
    int q = rem & 7;

    int node;
    if (s == 0)      node = __ldg(users + b);
    else if (s == 1) node = N_USERS + __ldg(pos + b);
    else             node = N_USERS + __ldg(neg + b);

    int beg  = __ldg(g_rowptr + node);
    int cnt2 = __ldg(g_rowptr + node + 1) - beg;
    const int* cp = g_ecol + beg;
    const uint4* B4 = reinterpret_cast<const uint4*>(g_XB);

    float2 c0[4] = {{0,0},{0,0},{0,0},{0,0}};
    for (int i = 0; i < cnt2; i += 2) {
        int2 c01 = *reinterpret_cast<const int2*>(cp + i);
        uint4 h0 = __ldg(B4 + (c01.x * 8 + q));
        uint4 h1 = __ldg(B4 + (c01.y * 8 + q));
        __half2 tx = __hadd2(u2h2(h0.x), u2h2(h1.x));
        __half2 ty = __hadd2(u2h2(h0.y), u2h2(h1.y));
        __half2 tz = __hadd2(u2h2(h0.z), u2h2(h1.z));
        __half2 tw = __hadd2(u2h2(h0.w), u2h2(h1.w));
        float2 p;
        p = __half22float2(tx); c0[0].x += p.x; c0[0].y += p.y;
        p = __half22float2(ty); c0[1].x += p.x; c0[1].y += p.y;
        p = __half22float2(tz); c0[2].x += p.x; c0[2].y += p.y;
        p = __half22float2(tw); c0[3].x += p.x; c0[3].y += p.y;
    }

    float dv = __ldg(g_dinv + node);
    float dp = __ldg(g_dpos + node);

    int off4 = node * 8 + q;
    uint4 ha = __ldg(reinterpret_cast<const uint4*>(g_XA) + off4);
    uint4 hb = __ldg(B4 + off4);
    size_t offf = (size_t)node * DIM + q * 8;
    float4 e00 = __ldg(reinterpret_cast<const float4*>(E0 + offf));
    float4 e01v = __ldg(reinterpret_cast<const float4*>(E0 + offf + 4));

    float2 pa, pb;
    float outv[8];
    pa = __half22float2(u2h2(ha.x)); pb = __half22float2(u2h2(hb.x));
    outv[0] = (e00.x + (pa.x + pb.x) * dp + dv * c0[0].x) * 0.25f;
    outv[1] = (e00.y + (pa.y + pb.y) * dp + dv * c0[0].y) * 0.25f;
    pa = __half22float2(u2h2(ha.y)); pb = __half22float2(u2h2(hb.y));
    outv[2] = (e00.z + (pa.x + pb.x) * dp + dv * c0[1].x) * 0.25f;
    outv[3] = (e00.w + (pa.y + pb.y) * dp + dv * c0[1].y) * 0.25f;
    pa = __half22float2(u2h2(ha.z)); pb = __half22float2(u2h2(hb.z));
    outv[4] = (e01v.x + (pa.x + pb.x) * dp + dv * c0[2].x) * 0.25f;
    outv[5] = (e01v.y + (pa.y + pb.y) * dp + dv * c0[2].y) * 0.25f;
    pa = __half22float2(u2h2(ha.w)); pb = __half22float2(u2h2(hb.w));
    outv[6] = (e01v.z + (pa.x + pb.x) * dp + dv * c0[3].x) * 0.25f;
    outv[7] = (e01v.w + (pa.y + pb.y) * dp + dv * c0[3].y) * 0.25f;

    const int S = BATCH * DIM;
    int o = b * DIM + q * 8;
    float4* op = reinterpret_cast<float4*>(out + (size_t)s * S + o);
    op[0] = make_float4(outv[0], outv[1], outv[2], outv[3]);
    op[1] = make_float4(outv[4], outv[5], outv[6], outv[7]);
    float4* oe = reinterpret_cast<float4*>(out + (size_t)(s + 3) * S + o);
    oe[0] = e00;
    oe[1] = e01v;
}

extern "C" void kernel_launch(void* const* d_in, const int* in_sizes, int n_in,
                              void* d_out, int out_size) {
    const int*   users = (const int*)d_in[0];
    const int*   pos   = (const int*)d_in[1];
    const int*   neg   = (const int*)d_in[2];
    const float* E0    = (const float*)d_in[3];
    const int*   row   = (const int*)d_in[4];
    const int*   col   = (const int*)d_in[5];
    const int    nnz   = in_sizes[4];

    __half *X0, *XA, *XB;
    cudaGetSymbolAddress((void**)&X0, g_X0);
    cudaGetSymbolAddress((void**)&XA, g_XA);
    cudaGetSymbolAddress((void**)&XB, g_XB);

    const int TB = 256;

    // CSR build + normalizers (counters zeroed by previous call / load-time init)
    int pairs = (nnz + 1) / 2;
    k_hist<<<(pairs + TB - 1) / TB, TB>>>(row, nnz);
    k_scan<<<NB, 1024>>>();

    // fused scatter + prep + re-zero, interleaved for intra-wave overlap
    const int n8 = N_TOTAL * DIM / 8;
    int quads = (nnz + 3) / 4;
    int sBlocks = (quads + TB - 1) / TB;
    int zBlocks = (N_TOTAL / 4 + TB - 1) / TB;
    int pBlocks = (n8 + TB - 1) / TB;
    int auxBlocks = sBlocks + zBlocks;
    int total = (pBlocks * 4 + 2) / 3;          // prep needs 3/4 of the grid
    if (total < auxBlocks * 4) total = auxBlocks * 4;
    total = (total + 3) & ~3;
    k_prep_scatter<<<total, TB>>>((const float4*)E0, row, col,
                                  nnz, sBlocks, zBlocks, pBlocks);

    // 2 scaled-space propagation layers
    const int spmmGrid = (N_TOTAL * 8 + TB - 1) / TB;
    k_spmm<<<spmmGrid, TB>>>(X0, XA);   // XA = Dinv2 * (A @ X0)
    k_spmm<<<spmmGrid, TB>>>(XA, XB);   // XB = Dinv2 * (A @ XA)

    // fused layer 3 + gather
    int outThreads = 3 * BATCH * 8;
    k_out<<<(outThreads + TB - 1) / TB, TB>>>(users, pos, neg, E0, (float*)d_out);
}

// round 16
// speedup vs baseline: 1.1846x; 1.0297x over previous
#include <cuda_runtime.h>
#include <cuda_fp16.h>

#define N_USERS  100000
#define N_TOTAL  150000
#define DIM      64
#define BATCH    4096
#define NNZ_MAX  1400000     // 1.2M edges + up to 150k pad slots
#define NBUCKET  256

#define SCAN_TILE 4096                                  // 1024 threads x 4 items
#define NB ((N_TOTAL + SCAN_TILE - 1) / SCAN_TILE)      // 37 blocks (all resident)

// Scaled-space embeddings X_k = d_inv ⊙ E_k, fp16, with one extra zero row
// (index N_TOTAL) used as the gather target of pad edges. All __device__
// globals are zero-initialized at module load; the sentinel rows are never
// written, so they stay zero. g_cnt / g_degcnt / scan flags are re-zeroed each
// call by the aux lane of k_prep_scatter (for the NEXT call).
__device__ __half g_X0[(N_TOTAL + 1) * DIM];
__device__ __half g_XA[(N_TOTAL + 1) * DIM];
__device__ __half g_XB[(N_TOTAL + 1) * DIM];
__device__ float g_dinv[N_TOTAL];        // (deg+1e-9)^-0.5
__device__ float g_dpos[N_TOTAL];        // (deg+1e-9)^+0.5  (to unscale)
__device__ int   g_cnt[N_TOTAL];         // true row degree (zeroed for next call)
__device__ int   g_rowptr[N_TOTAL + 1];  // padded exclusive scan (+ total at end)
__device__ int   g_rank[NNZ_MAX];        // intra-row rank per edge (from hist)
__device__ int   g_ecol[NNZ_MAX];        // CSR column indices; pad slots = N_TOTAL
__device__ int   g_perm[N_TOTAL];        // rows sorted by trip count (degree)
__device__ int   g_degcnt[NBUCKET];      // bucket histogram (zeroed for next call)
__device__ int   g_degcur[NBUCKET];      // bucket cursors (rewritten by degscan)
__device__ int   g_blockAgg[64];
__device__ int   g_aggReady[64];

__device__ __forceinline__ __half2 u2h2(unsigned u) {
    __half2 h; *reinterpret_cast<unsigned*>(&h) = u; return h;
}
__device__ __forceinline__ unsigned h22u(__half2 h) {
    return *reinterpret_cast<unsigned*>(&h);
}

// ---------------------------------------------------------------------------
// histogram of row ids, capturing each edge's intra-row rank (2 edges/thread)
__global__ void k_hist(const int* __restrict__ row, int nnz) {
    int t = blockIdx.x * blockDim.x + threadIdx.x;
    int base = t * 2;
    if (base + 2 <= nnz) {
        int2 r = __ldg(reinterpret_cast<const int2*>(row + base));
        int2 k;
        k.x = atomicAdd(&g_cnt[r.x], 1);
        k.y = atomicAdd(&g_cnt[r.y], 1);
        *reinterpret_cast<int2*>(g_rank + base) = k;
    } else if (base < nnz) {
        g_rank[base] = atomicAdd(&g_cnt[__ldg(row + base)], 1);
    }
}

// single-pass exclusive scan of padded counts -> rowptr (incl. total at
// rowptr[N_TOTAL]); derives degree normalizers; writes pad-edge sentinels;
// builds the bucket histogram (shared pre-aggregation -> spread global REDs).
__global__ void k_scan() {
    __shared__ int warpsum[32];
    __shared__ int s_aggs[64];
    __shared__ int s_prev;
    __shared__ int s_dh[NBUCKET];
    int tid  = threadIdx.x;
    int lane = tid & 31, wid = tid >> 5;
    int base = blockIdx.x * SCAN_TILE + tid * 4;

    if (tid < NBUCKET) s_dh[tid] = 0;

    int cc[4], cp[4];
#pragma unroll
    for (int k = 0; k < 4; k++) {
        int idx = base + k;
        cc[k] = (idx < N_TOTAL) ? g_cnt[idx] : 0;
        cp[k] = (cc[k] + 1) & ~1;                 // padded to even
    }
    int t = cp[0] + cp[1] + cp[2] + cp[3];

    __syncthreads();        // s_dh init visible
#pragma unroll
    for (int k = 0; k < 4; k++) {
        if (base + k < N_TOTAL) {
            int key = cp[k] >> 1;                 // pairs = trip count
            if (key > NBUCKET - 1) key = NBUCKET - 1;
            atomicAdd(&s_dh[key], 1);
        }
    }

    int x = t;
#pragma unroll
    for (int o = 1; o < 32; o <<= 1) {
        int y = __shfl_up_sync(0xffffffffu, x, o);
        if (lane >= o) x += y;
    }
    if (lane == 31) warpsum[wid] = x;
    __syncthreads();
    if (wid == 0) {
        int v = warpsum[lane];
#pragma unroll
        for (int o = 1; o < 32; o <<= 1) {
            int y = __shfl_up_sync(0xffffffffu, v, o);
            if (lane >= o) v += y;
        }
        warpsum[lane] = v;
    }
    __syncthreads();

    // flush block's bucket histogram (spread REDs, <=256 per block)
    if (tid < NBUCKET && s_dh[tid] > 0) atomicAdd(&g_degcnt[tid], s_dh[tid]);

    if (tid == 0) {
        g_blockAgg[blockIdx.x] = warpsum[31];
        __threadfence();
        atomicExch(&g_aggReady[blockIdx.x], 1);
    }
    if (tid < blockIdx.x) {
        while (atomicAdd(&g_aggReady[tid], 0) == 0) { }
        __threadfence();
        s_aggs[tid] = g_blockAgg[tid];
    }
    __syncthreads();
    if (tid == 0) {
        int p = 0;
        for (int j = 0; j < blockIdx.x; j++) p += s_aggs[j];
        s_prev = p;
    }
    __syncthreads();

    int woff = (wid == 0) ? 0 : warpsum[wid - 1];
    int run = s_prev + woff + (x - t);
#pragma unroll
    for (int k = 0; k < 4; k++) {
        int idx = base + k;
        if (idx < N_TOTAL) {
            g_rowptr[idx] = run;
            float degf = (float)cc[k] + 1e-9f;
            g_dinv[idx] = rsqrtf(degf);
            g_dpos[idx] = sqrtf(degf);
            if (cc[k] & 1) g_ecol[run + cc[k]] = N_TOTAL;   // pad -> zero row
            run += cp[k];
            if (idx == N_TOTAL - 1) g_rowptr[N_TOTAL] = run;  // total
        }
    }
}

// exclusive scan of the 256 bucket counts -> g_degcur (tiny, 1 block)
__global__ void k_degscan() {
    __shared__ int warpsum[8];
    int tid = threadIdx.x;            // 256 threads
    int lane = tid & 31, wid = tid >> 5;
    int v = g_degcnt[tid];
    int x = v;
#pragma unroll
    for (int o = 1; o < 32; o <<= 1) {
        int y = __shfl_up_sync(0xffffffffu, x, o);
        if (lane >= o) x += y;
    }
    if (lane == 31) warpsum[wid] = x;
    __syncthreads();
    if (wid == 0 && lane < 8) {
        int w = warpsum[lane];
#pragma unroll
        for (int o = 1; o < 8; o <<= 1) {
            int y = __shfl_up_sync(0xffu, w, o);
            if (lane >= o) w += y;
        }
        warpsum[lane] = w;
    }
    __syncthreads();
    int woff = (wid == 0) ? 0 : warpsum[wid - 1];
    g_degcur[tid] = woff + x - v;     // exclusive
}

// ---------------------------------------------------------------------------
// Fused scatter + perm-build + prep + counter-rezero; blocks interleaved by
// modulo so every wave mixes L2-latency-bound aux work with DRAM-bound prep.
__global__ void k_prep_scatter(const float4* __restrict__ E0,
                               const int* __restrict__ row,
                               const int* __restrict__ col,
                               int nnz, int sBlocks, int zBlocks, int mBlocks,
                               int pBlocks) {
    __shared__ int s_hist[NBUCKET];
    __shared__ int s_base[NBUCKET];
    unsigned b = blockIdx.x;
    if ((b & 3u) == 0u) {
        int aux = b >> 2;
        if (aux < sBlocks) {
            // ---- scatter: 4 edges/thread, slot = rowptr[row] + rank[edge]
            int t = aux * blockDim.x + threadIdx.x;
            int base = t * 4;
            if (base + 4 <= nnz) {
                int4 r = __ldg(reinterpret_cast<const int4*>(row + base));
                int4 c = __ldg(reinterpret_cast<const int4*>(col + base));
                int4 k = *reinterpret_cast<const int4*>(g_rank + base);
                g_ecol[__ldg(g_rowptr + r.x) + k.x] = c.x;
                g_ecol[__ldg(g_rowptr + r.y) + k.y] = c.y;
                g_ecol[__ldg(g_rowptr + r.z) + k.z] = c.z;
                g_ecol[__ldg(g_rowptr + r.w) + k.w] = c.w;
            } else {
                for (int e = base; e < nnz; e++) {
                    int rr = __ldg(row + e);
                    g_ecol[__ldg(g_rowptr + rr) + g_rank[e]] = __ldg(col + e);
                }
            }
        } else if (aux < sBlocks + zBlocks) {
            // ---- zero g_cnt + g_degcnt + scan flags for the NEXT call
            int zb = aux - sBlocks;
            int i = zb * blockDim.x + threadIdx.x;
            if (i < N_TOTAL / 4)
                reinterpret_cast<int4*>(g_cnt)[i] = make_int4(0, 0, 0, 0);
            if (zb == 0) {
                if (threadIdx.x < 16) {
                    reinterpret_cast<int4*>(g_aggReady)[threadIdx.x] = make_int4(0, 0, 0, 0);
                    reinterpret_cast<int4*>(g_blockAgg)[threadIdx.x] = make_int4(0, 0, 0, 0);
                }
                if (threadIdx.x < NBUCKET / 4)
                    reinterpret_cast<int4*>(g_degcnt)[threadIdx.x] = make_int4(0, 0, 0, 0);
            }
        } else if (aux < sBlocks + zBlocks + mBlocks) {
            // ---- perm build: counting-sort rows by trip count.
            // 3 phases: shared local ranks -> one global cursor atomic per
            // nonzero bucket -> scatter perm. All threads hit the syncs.
            int mb = aux - sBlocks - zBlocks;
            int i = mb * blockDim.x + threadIdx.x;
            bool valid = (i < N_TOTAL);
            s_hist[threadIdx.x] = 0;
            __syncthreads();
            int key = 0, lrank = 0;
            if (valid) {
                int cnt2 = __ldg(g_rowptr + i + 1) - __ldg(g_rowptr + i);
                key = cnt2 >> 1;
                if (key > NBUCKET - 1) key = NBUCKET - 1;
                lrank = atomicAdd(&s_hist[key], 1);
            }
            __syncthreads();
            int h = s_hist[threadIdx.x];
            if (h > 0) s_base[threadIdx.x] = atomicAdd(&g_degcur[threadIdx.x], h);
            __syncthreads();
            if (valid) g_perm[s_base[key] + lrank] = i;
        }
    } else {
        // ---- prep: X0 = fp16(d_inv[node] * E0), 8 floats per thread
        int pb = (int)b - (int)(b >> 2) - 1;     // rank among non-aux blocks
        if (pb >= pBlocks) return;
        int i = pb * blockDim.x + threadIdx.x;
        const int n8 = N_TOTAL * DIM / 8;
        if (i >= n8) return;
        float dv = __ldg(g_dinv + (i >> 3));     // 8 threads per node row
        float4 f0 = __ldg(E0 + i * 2);
        float4 f1 = __ldg(E0 + i * 2 + 1);
        uint4 h;
        h.x = h22u(__floats2half2_rn(dv * f0.x, dv * f0.y));
        h.y = h22u(__floats2half2_rn(dv * f0.z, dv * f0.w));
        h.z = h22u(__floats2half2_rn(dv * f1.x, dv * f1.y));
        h.w = h22u(__floats2half2_rn(dv * f1.z, dv * f1.w));
        reinterpret_cast<uint4*>(g_X0)[i] = h;
    }
}

// ---------------------------------------------------------------------------
// scaled-space SpMM over DEGREE-SORTED rows: node = perm[r], so the 4 rows a
// warp owns have (near-)identical trip counts -> no max-of-4 idle iterations.
// 8 threads/row, 8 dims/lane, 4-edge HADD2 tree + single fp32 flush per group.
__global__ void __launch_bounds__(256, 8)
k_spmm(const __half* __restrict__ src, __half* __restrict__ dst) {
    int t = blockIdx.x * blockDim.x + threadIdx.x;
    if (t >= N_TOTAL * 8) return;
    int q = t & 7;
    int node = __ldg(g_perm + (t >> 3));        // replaces r's live range

    int beg  = __ldg(g_rowptr + node);
    int cnt2 = __ldg(g_rowptr + node + 1) - beg;   // padded (even)
    const int* cp = g_ecol + beg;               // beg is even -> 8B aligned
    const uint4* src4 = reinterpret_cast<const uint4*>(src);

    float2 a0[4] = {{0,0},{0,0},{0,0},{0,0}};

    int i = 0;
    for (; i + 4 <= cnt2; i += 4) {
        int2 c01 = *reinterpret_cast<const int2*>(cp + i);
        int2 c23 = *reinterpret_cast<const int2*>(cp + i + 2);
        uint4 h0 = __ldg(src4 + (c01.x * 8 + q));
        uint4 h1 = __ldg(src4 + (c01.y * 8 + q));
        uint4 h2 = __ldg(src4 + (c23.x * 8 + q));
        uint4 h3 = __ldg(src4 + (c23.y * 8 + q));
        __half2 tx = __hadd2(__hadd2(u2h2(h0.x), u2h2(h1.x)),
                             __hadd2(u2h2(h2.x), u2h2(h3.x)));
        __half2 ty = __hadd2(__hadd2(u2h2(h0.y), u2h2(h1.y)),
                             __hadd2(u2h2(h2.y), u2h2(h3.y)));
        __half2 tz = __hadd2(__hadd2(u2h2(h0.z), u2h2(h1.z)),
                             __hadd2(u2h2(h2.z), u2h2(h3.z)));
        __half2 tw = __hadd2(__hadd2(u2h2(h0.w), u2h2(h1.w)),
                             __hadd2(u2h2(h2.w), u2h2(h3.w)));
        float2 p;
        p = __half22float2(tx); a0[0].x += p.x; a0[0].y += p.y;
        p = __half22float2(ty); a0[1].x += p.x; a0[1].y += p.y;
        p = __half22float2(tz); a0[2].x += p.x; a0[2].y += p.y;
        p = __half22float2(tw); a0[3].x += p.x; a0[3].y += p.y;
    }
    if (i < cnt2) {   // exactly 2 edges remain (cnt2 is even)
        int2 c01 = *reinterpret_cast<const int2*>(cp + i);
        uint4 h0 = __ldg(src4 + (c01.x * 8 + q));
        uint4 h1 = __ldg(src4 + (c01.y * 8 + q));
        __half2 tx = __hadd2(u2h2(h0.x), u2h2(h1.x));
        __half2 ty = __hadd2(u2h2(h0.y), u2h2(h1.y));
        __half2 tz = __hadd2(u2h2(h0.z), u2h2(h1.z));
        __half2 tw = __hadd2(u2h2(h0.w), u2h2(h1.w));
        float2 p;
        p = __half22float2(tx); a0[0].x += p.x; a0[0].y += p.y;
        p = __half22float2(ty); a0[1].x += p.x; a0[1].y += p.y;
        p = __half22float2(tz); a0[2].x += p.x; a0[2].y += p.y;
        p = __half22float2(tw); a0[3].x += p.x; a0[3].y += p.y;
    }

    float dv = __ldg(g_dinv + node);
    float s = dv * dv;
    uint4 o;
    o.x = h22u(__floats2half2_rn(a0[0].x * s, a0[0].y * s));
    o.y = h22u(__floats2half2_rn(a0[1].x * s, a0[1].y * s));
    o.z = h22u(__floats2half2_rn(a0[2].x * s, a0[2].y * s));
    o.w = h22u(__floats2half2_rn(a0[3].x * s, a0[3].y * s));
    reinterpret_cast<uint4*>(dst)[node * 8 + q] = o;
}

// ---------------------------------------------------------------------------
// Fused layer-3 + output. For each gathered node:
//   sum3 = sum_{c in N(node)} XB[c]          (scaled-space layer-3 gather)
//   final = (E0 + (XA+XB)[node]*dpos + dinv*sum3) / 4 ;  also emit E0.
__global__ void k_out(const int* __restrict__ users, const int* __restrict__ pos,
                      const int* __restrict__ neg, const float* __restrict__ E0,
                      float* __restrict__ out) {
    int t = blockIdx.x * blockDim.x + threadIdx.x;
    if (t >= 3 * BATCH * 8) return;
    int s = t >> 15;            // BATCH*8 = 32768
    int rem = t & 32767;
    int b = rem >> 3;
    int q = rem & 7;

    int node;
    if (s == 0)      node = __ldg(users + b);
    else if (s == 1) node = N_USERS + __ldg(pos + b);
    else             node = N_USERS + __ldg(neg + b);

    int beg  = __ldg(g_rowptr + node);
    int cnt2 = __ldg(g_rowptr + node + 1) - beg;
    const int* cp = g_ecol + beg;
    const uint4* B4 = reinterpret_cast<const uint4*>(g_XB);

    float2 c0[4] = {{0,0},{0,0},{0,0},{0,0}};
    for (int i = 0; i < cnt2; i += 2) {
        int2 c01 = *reinterpret_cast<const int2*>(cp + i);
        uint4 h0 = __ldg(B4 + (c01.x * 8 + q));
        uint4 h1 = __ldg(B4 + (c01.y * 8 + q));
        __half2 tx = __hadd2(u2h2(h0.x), u2h2(h1.x));
        __half2 ty = __hadd2(u2h2(h0.y), u2h2(h1.y));
        __half2 tz = __hadd2(u2h2(h0.z), u2h2(h1.z));
        __half2 tw = __hadd2(u2h2(h0.w), u2h2(h1.w));
        float2 p;
        p = __half22float2(tx); c0[0].x += p.x; c0[0].y += p.y;
        p = __half22float2(ty); c0[1].x += p.x; c0[1].y += p.y;
        p = __half22float2(tz); c0[2].x += p.x; c0[2].y += p.y;
        p = __half22float2(tw); c0[3].x += p.x; c0[3].y += p.y;
    }

    float dv = __ldg(g_dinv + node);
    float dp = __ldg(g_dpos + node);

    int off4 = node * 8 + q;
    uint4 ha = __ldg(reinterpret_cast<const uint4*>(g_XA) + off4);
    uint4 hb = __ldg(B4 + off4);
    size_t offf = (size_t)node * DIM + q * 8;
    float4 e00 = __ldg(reinterpret_cast<const float4*>(E0 + offf));
    float4 e01v = __ldg(reinterpret_cast<const float4*>(E0 + offf + 4));

    float2 pa, pb;
    float outv[8];
    pa = __half22float2(u2h2(ha.x)); pb = __half22float2(u2h2(hb.x));
    outv[0] = (e00.x + (pa.x + pb.x) * dp + dv * c0[0].x) * 0.25f;
    outv[1] = (e00.y + (pa.y + pb.y) * dp + dv * c0[0].y) * 0.25f;
    pa = __half22float2(u2h2(ha.y)); pb = __half22float2(u2h2(hb.y));
    outv[2] = (e00.z + (pa.x + pb.x) * dp + dv * c0[1].x) * 0.25f;
    outv[3] = (e00.w + (pa.y + pb.y) * dp + dv * c0[1].y) * 0.25f;
    pa = __half22float2(u2h2(ha.z)); pb = __half22float2(u2h2(hb.z));
    outv[4] = (e01v.x + (pa.x + pb.x) * dp + dv * c0[2].x) * 0.25f;
    outv[5] = (e01v.y + (pa.y + pb.y) * dp + dv * c0[2].y) * 0.25f;
    pa = __half22float2(u2h2(ha.w)); pb = __half22float2(u2h2(hb.w));
    outv[6] = (e01v.z + (pa.x + pb.x) * dp + dv * c0[3].x) * 0.25f;
    outv[7] = (e01v.w + (pa.y + pb.y) * dp + dv * c0[3].y) * 0.25f;

    const int S = BATCH * DIM;
    int o = b * DIM + q * 8;
    float4* op = reinterpret_cast<float4*>(out + (size_t)s * S + o);
    op[0] = make_float4(outv[0], outv[1], outv[2], outv[3]);
    op[1] = make_float4(outv[4], outv[5], outv[6], outv[7]);
    float4* oe = reinterpret_cast<float4*>(out + (size_t)(s + 3) * S + o);
    oe[0] = e00;
    oe[1] = e01v;
}

extern "C" void kernel_launch(void* const* d_in, const int* in_sizes, int n_in,
                              void* d_out, int out_size) {
    const int*   users = (const int*)d_in[0];
    const int*   pos   = (const int*)d_in[1];
    const int*   neg   = (const int*)d_in[2];
    const float* E0    = (const float*)d_in[3];
    const int*   row   = (const int*)d_in[4];
    const int*   col   = (const int*)d_in[5];
    const int    nnz   = in_sizes[4];

    __half *X0, *XA, *XB;
    cudaGetSymbolAddress((void**)&X0, g_X0);
    cudaGetSymbolAddress((void**)&XA, g_XA);
    cudaGetSymbolAddress((void**)&XB, g_XB);

    const int TB = 256;

    // CSR build + normalizers (counters zeroed by previous call / load-time init)
    int pairs = (nnz + 1) / 2;
    k_hist<<<(pairs + TB - 1) / TB, TB>>>(row, nnz);
    k_scan<<<NB, 1024>>>();
    k_degscan<<<1, NBUCKET>>>();

    // fused scatter + perm-build + prep + re-zero, interleaved for overlap
    const int n8 = N_TOTAL * DIM / 8;
    int quads = (nnz + 3) / 4;
    int sBlocks = (quads + TB - 1) / TB;
    int zBlocks = (N_TOTAL / 4 + TB - 1) / TB;
    int mBlocks = (N_TOTAL + TB - 1) / TB;
    int pBlocks = (n8 + TB - 1) / TB;
    int auxBlocks = sBlocks + zBlocks + mBlocks;
    int total = (pBlocks * 4 + 2) / 3;          // prep needs 3/4 of the grid
    if (total < auxBlocks * 4) total = auxBlocks * 4;
    total = (total + 3) & ~3;
    k_prep_scatter<<<total, TB>>>((const float4*)E0, row, col,
                                  nnz, sBlocks, zBlocks, mBlocks, pBlocks);

    // 2 scaled-space propagation layers over degree-sorted rows
    const int spmmGrid = (N_TOTAL * 8 + TB - 1) / TB;
    k_spmm<<<spmmGrid, TB>>>(X0, XA);   // XA = Dinv2 * (A @ X0)
    k_spmm<<<spmmGrid, TB>>>(XA, XB);   // XB = Dinv2 * (A @ XA)

    // fused layer 3 + gather
    int outThreads = 3 * BATCH * 8;
    k_out<<<(outThreads + TB - 1) / TB, TB>>>(users, pos, neg, E0, (float*)d_out);
}

// round 17
// speedup vs baseline: 1.1992x; 1.0124x over previous
#include <cuda_runtime.h>
#include <cuda_fp16.h>

#define N_USERS  100000
#define N_TOTAL  150000
#define DIM      64
#define BATCH    4096
#define NNZ_MAX  1400000     // 1.2M edges + up to 150k pad slots
#define NBUCKET  256

#define SCAN_TILE 4096                                  // 1024 threads x 4 items
#define NB ((N_TOTAL + SCAN_TILE - 1) / SCAN_TILE)      // 37 scan blocks

// Scaled-space embeddings X_k = d_inv ⊙ E_k, fp16, with one extra zero row
// (index N_TOTAL) used as the gather target of pad edges. All __device__
// globals are zero-initialized at module load; the sentinel rows are never
// written, so they stay zero. g_cnt / g_degcnt / g_degDone / scan flags are
// re-zeroed each call by k_scatter_aux (for the NEXT call).
__device__ __half g_X0[(N_TOTAL + 1) * DIM];
__device__ __half g_XA[(N_TOTAL + 1) * DIM];
__device__ __half g_XB[(N_TOTAL + 1) * DIM];
__device__ float g_dinv[N_TOTAL];        // (deg+1e-9)^-0.5
__device__ float g_dpos[N_TOTAL];        // (deg+1e-9)^+0.5  (to unscale)
__device__ int   g_cnt[N_TOTAL];         // true row degree (zeroed for next call)
__device__ int   g_rowptr[N_TOTAL + 1];  // padded exclusive scan (+ total at end)
__device__ int   g_rank[NNZ_MAX];        // intra-row rank per edge (from hist)
__device__ int   g_ecol[NNZ_MAX];        // CSR column indices; pad slots = N_TOTAL
__device__ int   g_perm[N_TOTAL];        // rows sorted by trip count (degree)
__device__ int   g_degcnt[NBUCKET];      // bucket histogram (zeroed for next call)
__device__ int   g_degcur[NBUCKET];      // bucket cursors (rewritten each call)
__device__ int   g_degDone;              // scan-block completion counter
__device__ int   g_blockAgg[64];
__device__ int   g_aggReady[64];

__device__ __forceinline__ __half2 u2h2(unsigned u) {
    __half2 h; *reinterpret_cast<unsigned*>(&h) = u; return h;
}
__device__ __forceinline__ unsigned h22u(__half2 h) {
    return *reinterpret_cast<unsigned*>(&h);
}

// ---------------------------------------------------------------------------
// histogram of row ids, capturing each edge's intra-row rank (2 edges/thread)
__global__ void k_hist(const int* __restrict__ row, int nnz) {
    int t = blockIdx.x * blockDim.x + threadIdx.x;
    int base = t * 2;
    if (base + 2 <= nnz) {
        int2 r = __ldg(reinterpret_cast<const int2*>(row + base));
        int2 k;
        k.x = atomicAdd(&g_cnt[r.x], 1);
        k.y = atomicAdd(&g_cnt[r.y], 1);
        *reinterpret_cast<int2*>(g_rank + base) = k;
    } else if (base < nnz) {
        g_rank[base] = atomicAdd(&g_cnt[__ldg(row + base)], 1);
    }
}

// ---------------------------------------------------------------------------
// Fused scan + prep. Blocks < NB run the rowptr scan (only 37 SMs of work —
// the old standalone scan left 75% of the chip idle); the remaining blocks
// stream X0 = fp16(d_inv * E0), computing d_inv locally from g_cnt (bit-
// identical rsqrtf). The last scan block to flush its bucket histogram also
// performs the 256-bucket exclusive scan (kills the separate 1-block launch).
__global__ void k_scanprep(const float4* __restrict__ E0) {
    __shared__ int warpsum[32];
    __shared__ int s_aggs[64];
    __shared__ int s_prev;
    __shared__ int s_dh[NBUCKET];
    __shared__ int s_last;
    __shared__ int s_ws8[8];

    if (blockIdx.x >= NB) {
        // ---- prep lane: 8 floats per thread
        int i = (blockIdx.x - NB) * blockDim.x + threadIdx.x;
        const int n8 = N_TOTAL * DIM / 8;
        if (i >= n8) return;
        int cnt = __ldg(g_cnt + (i >> 3));       // 8 threads per node row
        float dv = rsqrtf((float)cnt + 1e-9f);   // identical formula to scan
        float4 f0 = __ldg(E0 + i * 2);
        float4 f1 = __ldg(E0 + i * 2 + 1);
        uint4 h;
        h.x = h22u(__floats2half2_rn(dv * f0.x, dv * f0.y));
        h.y = h22u(__floats2half2_rn(dv * f0.z, dv * f0.w));
        h.z = h22u(__floats2half2_rn(dv * f1.x, dv * f1.y));
        h.w = h22u(__floats2half2_rn(dv * f1.z, dv * f1.w));
        reinterpret_cast<uint4*>(g_X0)[i] = h;
        return;
    }

    // ---- scan lane (1024 threads, 4 items each)
    int tid  = threadIdx.x;
    int lane = tid & 31, wid = tid >> 5;
    int base = blockIdx.x * SCAN_TILE + tid * 4;

    if (tid < NBUCKET) s_dh[tid] = 0;
    if (tid == 0) s_last = 0;

    int cc[4], cp[4];
#pragma unroll
    for (int k = 0; k < 4; k++) {
        int idx = base + k;
        cc[k] = (idx < N_TOTAL) ? g_cnt[idx] : 0;
        cp[k] = (cc[k] + 1) & ~1;                 // padded to even
    }
    int t = cp[0] + cp[1] + cp[2] + cp[3];

    __syncthreads();        // s_dh init visible
#pragma unroll
    for (int k = 0; k < 4; k++) {
        if (base + k < N_TOTAL) {
            int key = cp[k] >> 1;                 // pairs = trip count
            if (key > NBUCKET - 1) key = NBUCKET - 1;
            atomicAdd(&s_dh[key], 1);
        }
    }

    int x = t;
#pragma unroll
    for (int o = 1; o < 32; o <<= 1) {
        int y = __shfl_up_sync(0xffffffffu, x, o);
        if (lane >= o) x += y;
    }
    if (lane == 31) warpsum[wid] = x;
    __syncthreads();
    if (wid == 0) {
        int v = warpsum[lane];
#pragma unroll
        for (int o = 1; o < 32; o <<= 1) {
            int y = __shfl_up_sync(0xffffffffu, v, o);
            if (lane >= o) v += y;
        }
        warpsum[lane] = v;
    }
    __syncthreads();

    // flush block's bucket histogram (spread REDs) and arm completion counter
    if (tid < NBUCKET && s_dh[tid] > 0) atomicAdd(&g_degcnt[tid], s_dh[tid]);
    __syncthreads();        // all flushes of this block issued
    if (tid == 0) {
        __threadfence();
        if (atomicAdd(&g_degDone, 1) == NB - 1) s_last = 1;
    }

    if (tid == 0) {
        g_blockAgg[blockIdx.x] = warpsum[31];
        __threadfence();
        atomicExch(&g_aggReady[blockIdx.x], 1);
    }
    if (tid < blockIdx.x) {
        while (atomicAdd(&g_aggReady[tid], 0) == 0) { }
        __threadfence();
        s_aggs[tid] = g_blockAgg[tid];
    }
    __syncthreads();
    if (tid == 0) {
        int p = 0;
        for (int j = 0; j < blockIdx.x; j++) p += s_aggs[j];
        s_prev = p;
    }
    __syncthreads();

    int woff = (wid == 0) ? 0 : warpsum[wid - 1];
    int run = s_prev + woff + (x - t);
#pragma unroll
    for (int k = 0; k < 4; k++) {
        int idx = base + k;
        if (idx < N_TOTAL) {
            g_rowptr[idx] = run;
            float degf = (float)cc[k] + 1e-9f;
            g_dinv[idx] = rsqrtf(degf);
            g_dpos[idx] = sqrtf(degf);
            if (cc[k] & 1) g_ecol[run + cc[k]] = N_TOTAL;   // pad -> zero row
            run += cp[k];
            if (idx == N_TOTAL - 1) g_rowptr[N_TOTAL] = run;  // total
        }
    }

    // ---- last scan block: exclusive scan of bucket counts -> g_degcur
    __syncthreads();        // s_last visible to all
    if (s_last) {           // uniform per block -> syncthreads inside is legal
        int v = 0;
        if (tid < NBUCKET) v = atomicAdd(&g_degcnt[tid], 0);   // L2-coherent read
        int xx = v;
#pragma unroll
        for (int o = 1; o < 32; o <<= 1) {
            int y = __shfl_up_sync(0xffffffffu, xx, o);
            if (lane >= o) xx += y;
        }
        if (tid < NBUCKET && lane == 31) s_ws8[wid] = xx;
        __syncthreads();
        if (wid == 0 && lane < 8) {
            int w = s_ws8[lane];
#pragma unroll
            for (int o = 1; o < 8; o <<= 1) {
                int y = __shfl_up_sync(0xffu, w, o);
                if (lane >= o) w += y;
            }
            s_ws8[lane] = w;
        }
        __syncthreads();
        if (tid < NBUCKET) {
            int woff2 = (wid == 0) ? 0 : s_ws8[wid - 1];
            g_degcur[tid] = woff2 + xx - v;     // exclusive
        }
    }
}

// ---------------------------------------------------------------------------
// Fused scatter + counter-rezero + perm-build (all post-scan aux work).
__global__ void k_scatter_aux(const int* __restrict__ row,
                              const int* __restrict__ col,
                              int nnz, int sBlocks, int zBlocks) {
    __shared__ int s_hist[NBUCKET];
    __shared__ int s_base[NBUCKET];
    int b = blockIdx.x;
    if (b < sBlocks) {
        // ---- scatter: 4 edges/thread, slot = rowptr[row] + rank[edge]
        int t = b * blockDim.x + threadIdx.x;
        int base = t * 4;
        if (base + 4 <= nnz) {
            int4 r = __ldg(reinterpret_cast<const int4*>(row + base));
            int4 c = __ldg(reinterpret_cast<const int4*>(col + base));
            int4 k = *reinterpret_cast<const int4*>(g_rank + base);
            g_ecol[__ldg(g_rowptr + r.x) + k.x] = c.x;
            g_ecol[__ldg(g_rowptr + r.y) + k.y] = c.y;
            g_ecol[__ldg(g_rowptr + r.z) + k.z] = c.z;
            g_ecol[__ldg(g_rowptr + r.w) + k.w] = c.w;
        } else {
            for (int e = base; e < nnz; e++) {
                int rr = __ldg(row + e);
                g_ecol[__ldg(g_rowptr + rr) + g_rank[e]] = __ldg(col + e);
            }
        }
    } else if (b < sBlocks + zBlocks) {
        // ---- zero g_cnt + g_degcnt + g_degDone + scan flags for the NEXT call
        int zb = b - sBlocks;
        int i = zb * blockDim.x + threadIdx.x;
        if (i < N_TOTAL / 4)
            reinterpret_cast<int4*>(g_cnt)[i] = make_int4(0, 0, 0, 0);
        if (zb == 0) {
            if (threadIdx.x < 16) {
                reinterpret_cast<int4*>(g_aggReady)[threadIdx.x] = make_int4(0, 0, 0, 0);
                reinterpret_cast<int4*>(g_blockAgg)[threadIdx.x] = make_int4(0, 0, 0, 0);
            }
            if (threadIdx.x < NBUCKET / 4)
                reinterpret_cast<int4*>(g_degcnt)[threadIdx.x] = make_int4(0, 0, 0, 0);
            if (threadIdx.x == 0) g_degDone = 0;
        }
    } else {
        // ---- perm build: counting-sort rows by trip count (3 phases)
        int mb = b - sBlocks - zBlocks;
        int i = mb * blockDim.x + threadIdx.x;
        bool valid = (i < N_TOTAL);
        s_hist[threadIdx.x] = 0;
        __syncthreads();
        int key = 0, lrank = 0;
        if (valid) {
            int cnt2 = __ldg(g_rowptr + i + 1) - __ldg(g_rowptr + i);
            key = cnt2 >> 1;
            if (key > NBUCKET - 1) key = NBUCKET - 1;
            lrank = atomicAdd(&s_hist[key], 1);
        }
        __syncthreads();
        int h = s_hist[threadIdx.x];
        if (h > 0) s_base[threadIdx.x] = atomicAdd(&g_degcur[threadIdx.x], h);
        __syncthreads();
        if (valid) g_perm[s_base[key] + lrank] = i;
    }
}

// ---------------------------------------------------------------------------
// scaled-space SpMM over DEGREE-SORTED rows: node = perm[r], so the 4 rows a
// warp owns have (near-)identical trip counts -> no max-of-4 idle iterations.
// 8 threads/row, 8 dims/lane, 4-edge HADD2 tree + single fp32 flush per group.
__global__ void __launch_bounds__(256, 8)
k_spmm(const __half* __restrict__ src, __half* __restrict__ dst) {
    int t = blockIdx.x * blockDim.x + threadIdx.x;
    if (t >= N_TOTAL * 8) return;
    int q = t & 7;
    int node = __ldg(g_perm + (t >> 3));

    int beg  = __ldg(g_rowptr + node);
    int cnt2 = __ldg(g_rowptr + node + 1) - beg;   // padded (even)
    const int* cp = g_ecol + beg;               // beg is even -> 8B aligned
    const uint4* src4 = reinterpret_cast<const uint4*>(src);

    float2 a0[4] = {{0,0},{0,0},{0,0},{0,0}};

    int i = 0;
    for (; i + 4 <= cnt2; i += 4) {
        int2 c01 = *reinterpret_cast<const int2*>(cp + i);
        int2 c23 = *reinterpret_cast<const int2*>(cp + i + 2);
        uint4 h0 = __ldg(src4 + (c01.x * 8 + q));
        uint4 h1 = __ldg(src4 + (c01.y * 8 + q));
        uint4 h2 = __ldg(src4 + (c23.x * 8 + q));
        uint4 h3 = __ldg(src4 + (c23.y * 8 + q));
        __half2 tx = __hadd2(__hadd2(u2h2(h0.x), u2h2(h1.x)),
                             __hadd2(u2h2(h2.x), u2h2(h3.x)));
        __half2 ty = __hadd2(__hadd2(u2h2(h0.y), u2h2(h1.y)),
                             __hadd2(u2h2(h2.y), u2h2(h3.y)));
        __half2 tz = __hadd2(__hadd2(u2h2(h0.z), u2h2(h1.z)),
                             __hadd2(u2h2(h2.z), u2h2(h3.z)));
        __half2 tw = __hadd2(__hadd2(u2h2(h0.w), u2h2(h1.w)),
                             __hadd2(u2h2(h2.w), u2h2(h3.w)));
        float2 p;
        p = __half22float2(tx); a0[0].x += p.x; a0[0].y += p.y;
        p = __half22float2(ty); a0[1].x += p.x; a0[1].y += p.y;
        p = __half22float2(tz); a0[2].x += p.x; a0[2].y += p.y;
        p = __half22float2(tw); a0[3].x += p.x; a0[3].y += p.y;
    }
    if (i < cnt2) {   // exactly 2 edges remain (cnt2 is even)
        int2 c01 = *reinterpret_cast<const int2*>(cp + i);
        uint4 h0 = __ldg(src4 + (c01.x * 8 + q));
        uint4 h1 = __ldg(src4 + (c01.y * 8 + q));
        __half2 tx = __hadd2(u2h2(h0.x), u2h2(h1.x));
        __half2 ty = __hadd2(u2h2(h0.y), u2h2(h1.y));
        __half2 tz = __hadd2(u2h2(h0.z), u2h2(h1.z));
        __half2 tw = __hadd2(u2h2(h0.w), u2h2(h1.w));
        float2 p;
        p = __half22float2(tx); a0[0].x += p.x; a0[0].y += p.y;
        p = __half22float2(ty); a0[1].x += p.x; a0[1].y += p.y;
        p = __half22float2(tz); a0[2].x += p.x; a0[2].y += p.y;
        p = __half22float2(tw); a0[3].x += p.x; a0[3].y += p.y;
    }

    float dv = __ldg(g_dinv + node);
    float s = dv * dv;
    uint4 o;
    o.x = h22u(__floats2half2_rn(a0[0].x * s, a0[0].y * s));
    o.y = h22u(__floats2half2_rn(a0[1].x * s, a0[1].y * s));
    o.z = h22u(__floats2half2_rn(a0[2].x * s, a0[2].y * s));
    o.w = h22u(__floats2half2_rn(a0[3].x * s, a0[3].y * s));
    reinterpret_cast<uint4*>(dst)[node * 8 + q] = o;
}

// ---------------------------------------------------------------------------
// Fused layer-3 + output. For each gathered node:
//   sum3 = sum_{c in N(node)} XB[c]          (scaled-space layer-3 gather)
//   final = (E0 + (XA+XB)[node]*dpos + dinv*sum3) / 4 ;  also emit E0.
__global__ void k_out(const int* __restrict__ users, const int* __restrict__ pos,
                      const int* __restrict__ neg, const float* __restrict__ E0,
                      float* __restrict__ out) {
    int t = blockIdx.x * blockDim.x + threadIdx.x;
    if (t >= 3 * BATCH * 8) return;
    int s = t >> 15;            // BATCH*8 = 32768
    int rem = t & 32767;
    int b = rem >> 3;
    int q = rem & 7;

    int node;
    if (s == 0)      node = __ldg(users + b);
    else if (s == 1) node = N_USERS + __ldg(pos + b);
    else             node = N_USERS + __ldg(neg + b);

    int beg  = __ldg(g_rowptr + node);
    int cnt2 = __ldg(g_rowptr + node + 1) - beg;
    const int* cp = g_ecol + beg;
    const uint4* B4 = reinterpret_cast<const uint4*>(g_XB);

    float2 c0[4] = {{0,0},{0,0},{0,0},{0,0}};
    for (int i = 0; i < cnt2; i += 2) {
        int2 c01 = *reinterpret_cast<const int2*>(cp + i);
        uint4 h0 = __ldg(B4 + (c01.x * 8 + q));
        uint4 h1 = __ldg(B4 + (c01.y * 8 + q));
        __half2 tx = __hadd2(u2h2(h0.x), u2h2(h1.x));
        __half2 ty = __hadd2(u2h2(h0.y), u2h2(h1.y));
        __half2 tz = __hadd2(u2h2(h0.z), u2h2(h1.z));
        __half2 tw = __hadd2(u2h2(h0.w), u2h2(h1.w));
        float2 p;
        p = __half22float2(tx); c0[0].x += p.x; c0[0].y += p.y;
        p = __half22float2(ty); c0[1].x += p.x; c0[1].y += p.y;
        p = __half22float2(tz); c0[2].x += p.x; c0[2].y += p.y;
        p = __half22float2(tw); c0[3].x += p.x; c0[3].y += p.y;
    }

    float dv = __ldg(g_dinv + node);
    float dp = __ldg(g_dpos + node);

    int off4 = node * 8 + q;
    uint4 ha = __ldg(reinterpret_cast<const uint4*>(g_XA) + off4);
    uint4 hb = __ldg(B4 + off4);
    size_t offf = (size_t)node * DIM + q * 8;
    float4 e00 = __ldg(reinterpret_cast<const float4*>(E0 + offf));
    float4 e01v = __ldg(reinterpret_cast<const float4*>(E0 + offf + 4));

    float2 pa, pb;
    float outv[8];
    pa = __half22float2(u2h2(ha.x)); pb = __half22float2(u2h2(hb.x));
    outv[0] = (e00.x + (pa.x + pb.x) * dp + dv * c0[0].x) * 0.25f;
    outv[1] = (e00.y + (pa.y + pb.y) * dp + dv * c0[0].y) * 0.25f;
    pa = __half22float2(u2h2(ha.y)); pb = __half22float2(u2h2(hb.y));
    outv[2] = (e00.z + (pa.x + pb.x) * dp + dv * c0[1].x) * 0.25f;
    outv[3] = (e00.w + (pa.y + pb.y) * dp + dv * c0[1].y) * 0.25f;
    pa = __half22float2(u2h2(ha.z)); pb = __half22float2(u2h2(hb.z));
    outv[4] = (e01v.x + (pa.x + pb.x) * dp + dv * c0[2].x) * 0.25f;
    outv[5] = (e01v.y + (pa.y + pb.y) * dp + dv * c0[2].y) * 0.25f;
    pa = __half22float2(u2h2(ha.w)); pb = __half22float2(u2h2(hb.w));
    outv[6] = (e01v.z + (pa.x + pb.x) * dp + dv * c0[3].x) * 0.25f;
    outv[7] = (e01v.w + (pa.y + pb.y) * dp + dv * c0[3].y) * 0.25f;

    const int S = BATCH * DIM;
    int o = b * DIM + q * 8;
    float4* op = reinterpret_cast<float4*>(out + (size_t)s * S + o);
    op[0] = make_float4(outv[0], outv[1], outv[2], outv[3]);
    op[1] = make_float4(outv[4], outv[5], outv[6], outv[7]);
    float4* oe = reinterpret_cast<float4*>(out + (size_t)(s + 3) * S + o);
    oe[0] = e00;
    oe[1] = e01v;
}

extern "C" void kernel_launch(void* const* d_in, const int* in_sizes, int n_in,
                              void* d_out, int out_size) {
    const int*   users = (const int*)d_in[0];
    const int*   pos   = (const int*)d_in[1];
    const int*   neg   = (const int*)d_in[2];
    const float* E0    = (const float*)d_in[3];
    const int*   row   = (const int*)d_in[4];
    const int*   col   = (const int*)d_in[5];
    const int    nnz   = in_sizes[4];

    __half *X0, *XA, *XB;
    cudaGetSymbolAddress((void**)&X0, g_X0);
    cudaGetSymbolAddress((void**)&XA, g_XA);
    cudaGetSymbolAddress((void**)&XB, g_XB);

    const int TB = 256;

    // CSR histogram (counters zeroed by previous call / load-time init)
    int pairs = (nnz + 1) / 2;
    k_hist<<<(pairs + TB - 1) / TB, TB>>>(row, nnz);

    // fused scan + prep (+ in-kernel degscan): scan uses 37 blocks, prep fills
    // the remaining SMs with the DRAM-bound E0->X0 conversion
    const int n8 = N_TOTAL * DIM / 8;
    int prepBlocks1024 = (n8 + 1023) / 1024;
    k_scanprep<<<NB + prepBlocks1024, 1024>>>((const float4*)E0);

    // fused scatter + re-zero + perm build
    int quads = (nnz + 3) / 4;
    int sBlocks = (quads + TB - 1) / TB;
    int zBlocks = (N_TOTAL / 4 + TB - 1) / TB;
    int mBlocks = (N_TOTAL + TB - 1) / TB;
    k_scatter_aux<<<sBlocks + zBlocks + mBlocks, TB>>>(row, col, nnz,
                                                       sBlocks, zBlocks);

    // 2 scaled-space propagation layers over degree-sorted rows
    const int spmmGrid = (N_TOTAL * 8 + TB - 1) / TB;
    k_spmm<<<spmmGrid, TB>>>(X0, XA);   // XA = Dinv2 * (A @ X0)
    k_spmm<<<spmmGrid, TB>>>(XA, XB);   // XB = Dinv2 * (A @ XA)

    // fused layer 3 + gather
    int outThreads = 3 * BATCH * 8;
    k_out<<<(outThreads + TB - 1) / TB, TB>>>(users, pos, neg, E0, (float*)d_out);
}